// round 13
// baseline (speedup 1.0000x reference)
#include <cuda_runtime.h>
#include <cuda_bf16.h>
#include <cstdint>

// ---------------- problem constants (fixed by setup_inputs) ----------------
#define BATCH   32
#define NNODE   512
#define NROWS   (BATCH*NNODE)      // 16384
#define FDIM    1024
#define H1      512
#define H2      256
#define H3      128
#define NC      8
#define EDGES   32768              // per batch
#define NEDGE   (BATCH*EDGES)      // 1048576
#define EH      64
#define EC      10
#define CATTR   9
#define NODE_OUT_ELEMS (NROWS*NC)  // 131072

// ---------------- scratch (device globals; no allocation allowed) ----------
__device__ __nv_bfloat16 g_x[NROWS * FDIM];     // bf16 roi
__device__ __nv_bfloat16 g_h1[NROWS * H1];
__device__ __nv_bfloat16 g_h2[NROWS * H2];
__device__ __nv_bfloat16 g_w1t[H1 * FDIM];
__device__ __nv_bfloat16 g_w2t[H2 * H1];
__device__ __nv_bfloat16 g_w3t[H3 * H2];
__device__ __nv_bfloat16 g_ew1t[64 * 32];
__device__ __nv_bfloat16 g_ew2t[64 * 64];
__device__ __nv_bfloat16 g_ew3t[16 * 64];

// ---------------- helpers ----------------------------------------------------
__device__ __forceinline__ uint32_t smem_u32(const void* p) {
    uint32_t a;
    asm("{ .reg .u64 t; cvta.to.shared.u64 t, %1; cvt.u32.u64 %0, t; }"
        : "=r"(a) : "l"(p));
    return a;
}
__device__ __forceinline__ void ldsm4(uint32_t addr, uint32_t* r) {
    asm volatile("ldmatrix.sync.aligned.m8n8.x4.shared.b16 {%0,%1,%2,%3}, [%4];"
                 : "=r"(r[0]), "=r"(r[1]), "=r"(r[2]), "=r"(r[3]) : "r"(addr));
}
__device__ __forceinline__ void mma16816(float* c, const uint32_t* a, const uint32_t* b) {
    asm volatile(
        "mma.sync.aligned.m16n8k16.row.col.f32.bf16.bf16.f32 "
        "{%0,%1,%2,%3}, {%4,%5,%6,%7}, {%8,%9}, {%0,%1,%2,%3};"
        : "+f"(c[0]), "+f"(c[1]), "+f"(c[2]), "+f"(c[3])
        : "r"(a[0]), "r"(a[1]), "r"(a[2]), "r"(a[3]), "r"(b[0]), "r"(b[1]));
}
__device__ __forceinline__ void sts128(uint32_t addr, uint4 v) {
    asm volatile("st.shared.v4.b32 [%0], {%1,%2,%3,%4};"
                 :: "r"(addr), "r"(v.x), "r"(v.y), "r"(v.z), "r"(v.w) : "memory");
}
__device__ __forceinline__ uint32_t pack_bf2(float a, float b) {
    __nv_bfloat162 h = __floats2bfloat162_rn(a, b);
    uint32_t u; memcpy(&u, &h, 4); return u;
}
__device__ __forceinline__ void cp16(uint32_t dst, const void* src) {
    asm volatile("cp.async.cg.shared.global [%0], [%1], 16;"
                 :: "r"(dst), "l"(src) : "memory");
}
__device__ __forceinline__ void cp_commit() {
    asm volatile("cp.async.commit_group;" ::: "memory");
}
#define CP_WAIT(n) asm volatile("cp.async.wait_group %0;" :: "n"(n) : "memory")

// ---------------- single-pass bf16 mma GEMM, cp.async 3-stage pipeline ------
// K-chunk = 64 (128-byte smem rows, c^(r&7) swizzle), 3 stages.
// OMODE: 0 = fp32 out, 1 = bf16 out, 2 = fused node head.
static constexpr int STAGE_BYTES = 32768;   // A|B x 16KB (128 rows x 128B)
static constexpr int GEMM_SMEM = 3 * STAGE_BYTES;       // 96KB
static constexpr int GEMM3_SMEM = GEMM_SMEM;            // head tile 67584 < 96KB

template<int K, int N, int EPI, int OMODE>
__global__ __launch_bounds__(256)
void gemm_mma2(const __nv_bfloat16* __restrict__ A,
               const __nv_bfloat16* __restrict__ B,
               const float* __restrict__ bias,
               const float* __restrict__ bng, const float* __restrict__ bnb,
               const float* __restrict__ bnrm, const float* __restrict__ bnrv,
               const float* __restrict__ hw,  const float* __restrict__ hb,
               float* __restrict__ Cf,
               __nv_bfloat16* __restrict__ Cb)
{
    extern __shared__ char sm_raw[];
    const uint32_t sb = smem_u32(sm_raw);
    const int tid = threadIdx.x;
    const int lane = tid & 31, w = tid >> 5;
    const int bn = blockIdx.x, bm = blockIdx.y;
    const int wr = (w & 3) * 32;
    const int wc = (w >> 2) * 64;

    // ---- per-thread async-copy slots: 8 x 16B per stage (A|B, 128B rows) ----
    const __nv_bfloat16* srcs[8];
    uint32_t dsts[8];
    #pragma unroll
    for (int i = 0; i < 8; i++) {
        int idx = i * 256 + tid;          // 0..2047
        int slab = idx >> 10;             // 0:A 1:B
        int within = idx & 1023;
        int r = within >> 3, c = within & 7;
        const __nv_bfloat16* base = (slab == 0) ? A : B;
        int row0 = (slab == 0) ? bm * 128 : bn * 128;
        srcs[i] = base + (size_t)(row0 + r) * K + c * 8;
        dsts[i] = slab * 16384 + r * 128 + ((c ^ (r & 7)) << 4);
    }
    auto ISSUE = [&](int ck) {
        const uint32_t st = sb + (ck % 3) * STAGE_BYTES;
        #pragma unroll
        for (int i = 0; i < 8; i++)
            cp16(st + dsts[i], srcs[i] + ck * 64);
    };

    float acc[2][8][4];
    #pragma unroll
    for (int a = 0; a < 2; a++)
        #pragma unroll
        for (int b = 0; b < 8; b++)
            #pragma unroll
            for (int c = 0; c < 4; c++) acc[a][b][c] = 0.f;

    const int m = lane >> 3, rr = lane & 7;

    auto COMPUTE = [&](int stage) {
        const uint32_t aB = sb + stage * STAGE_BYTES;
        const uint32_t bB = aB + 16384;
        #pragma unroll
        for (int ks = 0; ks < 4; ks++) {
            const int ckb = ks * 2;
            uint32_t ah[2][4], bh[4][4];
            #pragma unroll
            for (int t2 = 0; t2 < 2; t2++) {
                const int r_l = wr + t2 * 16 + ((m & 1) << 3) + rr;
                const int c_l = ckb + (m >> 1);
                const uint32_t off = r_l * 128 + ((c_l ^ (r_l & 7)) << 4);
                ldsm4(aB + off, ah[t2]);
            }
            #pragma unroll
            for (int p = 0; p < 4; p++) {
                const int n_l = wc + p * 16 + ((m >> 1) << 3) + rr;
                const int c_l = ckb + (m & 1);
                const uint32_t off = n_l * 128 + ((c_l ^ (n_l & 7)) << 4);
                ldsm4(bB + off, bh[p]);
            }
            #pragma unroll
            for (int t2 = 0; t2 < 2; t2++)
                #pragma unroll
                for (int nt = 0; nt < 8; nt++)
                    mma16816(acc[t2][nt], ah[t2], &bh[nt >> 1][(nt & 1) * 2]);
        }
    };

    constexpr int NCH = K / 64;
    ISSUE(0); cp_commit();
    ISSUE(1); cp_commit();
    for (int c = 0; c < NCH; c++) {
        CP_WAIT(1);
        __syncthreads();
        if (c + 2 < NCH) ISSUE(c + 2);
        cp_commit();
        COMPUTE(c % 3);
    }

    float* sh3 = (float*)sm_raw;
    if (OMODE == 2) __syncthreads();

    #pragma unroll
    for (int t2 = 0; t2 < 2; t2++) {
        const int rloc = wr + t2 * 16 + (lane >> 2);
        const int row0 = bm * 128 + rloc;
        #pragma unroll
        for (int nt = 0; nt < 8; nt++) {
            const int cloc = wc + nt * 8 + 2 * (lane & 3);
            const int col = bn * 128 + cloc;
            float b0 = __ldg(&bias[col]), b1 = __ldg(&bias[col + 1]);
            float s0 = 1.f, s1 = 1.f, f0 = 0.f, f1 = 0.f;
            if (EPI) {
                s0 = __ldg(&bng[col]) * rsqrtf(__ldg(&bnrv[col]) + 1e-5f);
                f0 = __ldg(&bnb[col]) - __ldg(&bnrm[col]) * s0;
                s1 = __ldg(&bng[col + 1]) * rsqrtf(__ldg(&bnrv[col + 1]) + 1e-5f);
                f1 = __ldg(&bnb[col + 1]) - __ldg(&bnrm[col + 1]) * s1;
            }
            float v00 = acc[t2][nt][0] + b0, v01 = acc[t2][nt][1] + b1;
            float v10 = acc[t2][nt][2] + b0, v11 = acc[t2][nt][3] + b1;
            if (EPI) {
                v00 = v00 * s0 + f0; v01 = v01 * s1 + f1;
                v10 = v10 * s0 + f0; v11 = v11 * s1 + f1;
            }
            v00 = fmaxf(v00, 0.f); v01 = fmaxf(v01, 0.f);
            v10 = fmaxf(v10, 0.f); v11 = fmaxf(v11, 0.f);
            if (OMODE == 1) {
                __nv_bfloat162 h0 = __floats2bfloat162_rn(v00, v01);
                __nv_bfloat162 h1 = __floats2bfloat162_rn(v10, v11);
                *(__nv_bfloat162*)(Cb + (size_t)row0 * N + col) = h0;
                *(__nv_bfloat162*)(Cb + (size_t)(row0 + 8) * N + col) = h1;
            } else if (OMODE == 2) {
                sh3[rloc * 132 + cloc]       = v00;
                sh3[rloc * 132 + cloc + 1]   = v01;
                sh3[(rloc + 8) * 132 + cloc]     = v10;
                sh3[(rloc + 8) * 132 + cloc + 1] = v11;
            } else {
                *(float2*)(Cf + (size_t)row0 * N + col) = make_float2(v00, v01);
                *(float2*)(Cf + (size_t)(row0 + 8) * N + col) = make_float2(v10, v11);
            }
        }
    }

    if (OMODE == 2) {
        __syncthreads();
        const int base = tid * 4;
        #pragma unroll
        for (int i = 0; i < 4; i++) {
            const int idx = base + i;
            const int row = idx >> 3;
            const int j = idx & 7;
            const float* xr = &sh3[row * 132];
            float a = __ldg(&hb[j]);
            #pragma unroll 8
            for (int k = 0; k < H3; k++)
                a += xr[k] * __ldg(&hw[k * NC + j]);
            Cf[(size_t)(bm * 128 + row) * NC + j] = 1.f / (1.f + __expf(-a));
        }
    }
}

// ---------------- fp32 -> bf16 convert (for roi) ----------------------------
__global__ __launch_bounds__(256)
void convert_f32(const float4* __restrict__ in, uint2* __restrict__ ob)
{
    int i = blockIdx.x * 256 + threadIdx.x;
    float4 v = in[i];
    __nv_bfloat162 h0 = __floats2bfloat162_rn(v.x, v.y);
    __nv_bfloat162 h1 = __floats2bfloat162_rn(v.z, v.w);
    uint2 u;
    memcpy(&u.x, &h0, 4); memcpy(&u.y, &h1, 4);
    ob[i] = u;
}

// ------- weight transpose to bf16 (coalesced, SMEM-tiled) -------------------
__global__ void transpose_bf16(const float* __restrict__ in,
                               __nv_bfloat16* __restrict__ ob,
                               int R, int C)
{
    __shared__ float t[32][33];
    int x = blockIdx.x * 32 + threadIdx.x;
    int y = blockIdx.y * 32 + threadIdx.y;
    #pragma unroll
    for (int i = 0; i < 32; i += 8)
        t[threadIdx.y + i][threadIdx.x] = in[(size_t)(y + i) * C + x];
    __syncthreads();
    x = blockIdx.y * 32 + threadIdx.x;
    y = blockIdx.x * 32 + threadIdx.y;
    #pragma unroll
    for (int i = 0; i < 32; i += 8)
        ob[(size_t)(y + i) * R + x] = __float2bfloat16(t[threadIdx.x][threadIdx.y + i]);
}

// ---------------- edge weight prep: transpose+pad to bf16 -------------------
__global__ void prep_edge_weights(const float* __restrict__ w1,
                                  const float* __restrict__ w2,
                                  const float* __restrict__ wi,
                                  __nv_bfloat16* __restrict__ o1,
                                  __nv_bfloat16* __restrict__ o2,
                                  __nv_bfloat16* __restrict__ o3)
{
    int t = blockIdx.x * 256 + threadIdx.x;
    int stride = gridDim.x * 256;
    for (int i = t; i < 64 * 32; i += stride) {
        int n = i >> 5, k = i & 31;
        o1[i] = (k < 18) ? __float2bfloat16(w1[k * 64 + n]) : __nv_bfloat16(0.f);
    }
    for (int i = t; i < 64 * 64; i += stride) {
        int n = i >> 6, k = i & 63;
        o2[i] = __float2bfloat16(w2[k * 64 + n]);
    }
    for (int i = t; i < 16 * 64; i += stride) {
        int n = i >> 6, k = i & 63;
        o3[i] = (n < EC) ? __float2bfloat16(wi[k * EC + n]) : __nv_bfloat16(0.f);
    }
}

// ---------------- edge MLP: register-chained B2B mma (verified R10) ---------
// 256 edges / 8 warps per CTA; warp w owns rows [wrow, wrow+32).
static constexpr int ESA_ATTR = 0;            // 512*10*2  = 10240
static constexpr int ESA_W1   = 10240;        //  4096
static constexpr int ESA_W2   = 14336;        //  8192
static constexpr int ESA_W3   = 22528;        //  2048
static constexpr int ESA_A1   = 24576;        // 256*64 = 16384
static constexpr int EDGE_SMEM = 40960;

__global__ __launch_bounds__(256)
void edge_mma_kernel(const float* __restrict__ bboxes,
                     const float* __restrict__ dirs,
                     const float* __restrict__ prio,
                     const int*   __restrict__ eidx,
                     const __nv_bfloat16* __restrict__ w1t,
                     const __nv_bfloat16* __restrict__ w2t,
                     const __nv_bfloat16* __restrict__ w3t,
                     const float* __restrict__ b1,
                     const float* __restrict__ b2,
                     const float* __restrict__ bi,
                     float* __restrict__ out)
{
    extern __shared__ char sm[];
    const uint32_t sb = smem_u32(sm);
    const int tid = threadIdx.x;
    const int lane = tid & 31, w = tid >> 5;
    const int bt = blockIdx.x >> 7;
    const int e0 = (blockIdx.x & 127) * 256;

    __nv_bfloat16* sAttr = (__nv_bfloat16*)(sm + ESA_ATTR);
    const float inv = 1.f / 1024.f;
    for (int n = tid; n < NNODE; n += 256) {
        int gn = bt * NNODE + n;
        float4 bb = *(const float4*)&bboxes[(size_t)gn * 4];
        float4 dd = *(const float4*)&dirs[(size_t)gn * 4];
        float pr = prio[gn];
        __nv_bfloat16* a = sAttr + n * 10;
        a[0] = __float2bfloat16(bb.x * inv);
        a[1] = __float2bfloat16(bb.y * inv);
        a[2] = __float2bfloat16(bb.z * inv);
        a[3] = __float2bfloat16(bb.w * inv);
        a[4] = __float2bfloat16(dd.x);
        a[5] = __float2bfloat16(dd.y);
        a[6] = __float2bfloat16(dd.z);
        a[7] = __float2bfloat16(dd.w);
        a[8] = __float2bfloat16(pr);
    }
    for (int i = tid; i < 64 * 4; i += 256) {
        int r = i >> 2, c = i & 3;
        uint4 v = ((const uint4*)w1t)[r * 4 + c];
        sts128(sb + ESA_W1 + r * 64 + ((c ^ ((r >> 1) & 3)) << 4), v);
    }
    for (int i = tid; i < 64 * 8; i += 256) {
        int r = i >> 3, c = i & 7;
        uint4 v = ((const uint4*)w2t)[r * 8 + c];
        sts128(sb + ESA_W2 + r * 128 + ((c ^ (r & 7)) << 4), v);
    }
    for (int i = tid; i < 16 * 8; i += 256) {
        int r = i >> 3, c = i & 7;
        uint4 v = ((const uint4*)w3t)[r * 8 + c];
        sts128(sb + ESA_W3 + r * 128 + ((c ^ (r & 7)) << 4), v);
    }
    __syncthreads();

    {
        const int ebase = bt * 2 * EDGES + e0 + tid;
        const int src = eidx[ebase];
        const int dst = eidx[ebase + EDGES];
        const __nv_bfloat16* as = sAttr + src * 10;
        const __nv_bfloat16* ad = sAttr + dst * 10;
        uint16_t v[32];
        #pragma unroll
        for (int c = 0; c < 9; c++) { memcpy(&v[c], &as[c], 2); memcpy(&v[9 + c], &ad[c], 2); }
        #pragma unroll
        for (int c = 18; c < 32; c++) v[c] = 0;
        const int swz = (tid >> 1) & 3;
        #pragma unroll
        for (int ch = 0; ch < 4; ch++) {
            uint4 p;
            p.x = (uint32_t)v[ch*8+0] | ((uint32_t)v[ch*8+1] << 16);
            p.y = (uint32_t)v[ch*8+2] | ((uint32_t)v[ch*8+3] << 16);
            p.z = (uint32_t)v[ch*8+4] | ((uint32_t)v[ch*8+5] << 16);
            p.w = (uint32_t)v[ch*8+6] | ((uint32_t)v[ch*8+7] << 16);
            sts128(sb + ESA_A1 + tid * 64 + ((ch ^ swz) << 4), p);
        }
    }
    __syncwarp();

    const int m = lane >> 3, rr = lane & 7;
    const int wrow = (w >> 2) * 128 + (w & 3) * 32;
    const int t4 = 2 * (lane & 3);

    #pragma unroll
    for (int t2 = 0; t2 < 2; t2++) {
        const int rbase = wrow + t2 * 16;

        float acc1[8][4];
        #pragma unroll
        for (int b = 0; b < 8; b++)
            #pragma unroll
            for (int c = 0; c < 4; c++) acc1[b][c] = 0.f;
        #pragma unroll
        for (int k16 = 0; k16 < 2; k16++) {
            uint32_t a[4], b[4][4];
            {
                int r = rbase + ((m & 1) << 3) + rr;
                int c = k16 * 2 + (m >> 1);
                ldsm4(sb + ESA_A1 + r * 64 + ((c ^ ((r >> 1) & 3)) << 4), a);
            }
            #pragma unroll
            for (int p = 0; p < 4; p++) {
                int n = p * 16 + ((m >> 1) << 3) + rr;
                int c = k16 * 2 + (m & 1);
                ldsm4(sb + ESA_W1 + n * 64 + ((c ^ ((n >> 1) & 3)) << 4), b[p]);
            }
            #pragma unroll
            for (int nt = 0; nt < 8; nt++)
                mma16816(acc1[nt], a, &b[nt >> 1][(nt & 1) * 2]);
        }

        uint32_t a2[4][4];
        #pragma unroll
        for (int kk = 0; kk < 4; kk++) {
            const int ntA = 2 * kk, ntB = ntA + 1;
            const int colA = ntA * 8 + t4, colB = ntB * 8 + t4;
            float bA0 = __ldg(&b1[colA]), bA1 = __ldg(&b1[colA + 1]);
            float bB0 = __ldg(&b1[colB]), bB1 = __ldg(&b1[colB + 1]);
            a2[kk][0] = pack_bf2(fmaxf(acc1[ntA][0] + bA0, 0.f),
                                 fmaxf(acc1[ntA][1] + bA1, 0.f));
            a2[kk][1] = pack_bf2(fmaxf(acc1[ntA][2] + bA0, 0.f),
                                 fmaxf(acc1[ntA][3] + bA1, 0.f));
            a2[kk][2] = pack_bf2(fmaxf(acc1[ntB][0] + bB0, 0.f),
                                 fmaxf(acc1[ntB][1] + bB1, 0.f));
            a2[kk][3] = pack_bf2(fmaxf(acc1[ntB][2] + bB0, 0.f),
                                 fmaxf(acc1[ntB][3] + bB1, 0.f));
        }

        float acc2[8][4];
        #pragma unroll
        for (int b = 0; b < 8; b++)
            #pragma unroll
            for (int c = 0; c < 4; c++) acc2[b][c] = 0.f;
        #pragma unroll
        for (int kk = 0; kk < 4; kk++) {
            uint32_t b[4][4];
            #pragma unroll
            for (int p = 0; p < 4; p++) {
                int n = p * 16 + ((m >> 1) << 3) + rr;
                int c = kk * 2 + (m & 1);
                ldsm4(sb + ESA_W2 + n * 128 + ((c ^ (n & 7)) << 4), b[p]);
            }
            #pragma unroll
            for (int nt = 0; nt < 8; nt++)
                mma16816(acc2[nt], a2[kk], &b[nt >> 1][(nt & 1) * 2]);
        }

        uint32_t a3[4][4];
        #pragma unroll
        for (int kk = 0; kk < 4; kk++) {
            const int ntA = 2 * kk, ntB = ntA + 1;
            const int colA = ntA * 8 + t4, colB = ntB * 8 + t4;
            float bA0 = __ldg(&b2[colA]), bA1 = __ldg(&b2[colA + 1]);
            float bB0 = __ldg(&b2[colB]), bB1 = __ldg(&b2[colB + 1]);
            a3[kk][0] = pack_bf2(fmaxf(acc2[ntA][0] + bA0, 0.f),
                                 fmaxf(acc2[ntA][1] + bA1, 0.f));
            a3[kk][1] = pack_bf2(fmaxf(acc2[ntA][2] + bA0, 0.f),
                                 fmaxf(acc2[ntA][3] + bA1, 0.f));
            a3[kk][2] = pack_bf2(fmaxf(acc2[ntB][0] + bB0, 0.f),
                                 fmaxf(acc2[ntB][1] + bB1, 0.f));
            a3[kk][3] = pack_bf2(fmaxf(acc2[ntB][2] + bB0, 0.f),
                                 fmaxf(acc2[ntB][3] + bB1, 0.f));
        }

        float acc3[2][4];
        #pragma unroll
        for (int b = 0; b < 2; b++)
            #pragma unroll
            for (int c = 0; c < 4; c++) acc3[b][c] = 0.f;
        #pragma unroll
        for (int kk = 0; kk < 4; kk++) {
            uint32_t b[4];
            int n = ((m >> 1) << 3) + rr;
            int c = kk * 2 + (m & 1);
            ldsm4(sb + ESA_W3 + n * 128 + ((c ^ (n & 7)) << 4), b);
            mma16816(acc3[0], a3[kk], &b[0]);
            mma16816(acc3[1], a3[kk], &b[2]);
        }

        const int r0 = rbase + (lane >> 2);
        const long eg = (long)bt * EDGES + e0 + r0;
        #pragma unroll
        for (int nt = 0; nt < 2; nt++) {
            const int col = nt * 8 + t4;
            if (col < EC) {
                float bb0 = __ldg(&bi[col]), bb1 = __ldg(&bi[col + 1]);
                float s00 = 1.f / (1.f + __expf(-(acc3[nt][0] + bb0)));
                float s01 = 1.f / (1.f + __expf(-(acc3[nt][1] + bb1)));
                float s10 = 1.f / (1.f + __expf(-(acc3[nt][2] + bb0)));
                float s11 = 1.f / (1.f + __expf(-(acc3[nt][3] + bb1)));
                *(float2*)(out + eg * EC + col) = make_float2(s00, s01);
                *(float2*)(out + (eg + 8) * EC + col) = make_float2(s10, s11);
            }
        }
    }
}

// ---------------- launch ----------------------------------------------------
extern "C" void kernel_launch(void* const* d_in, const int* in_sizes, int n_in,
                              void* d_out, int out_size)
{
    const float* roi    = (const float*)d_in[0];
    const float* bboxes = (const float*)d_in[1];
    const float* dirs   = (const float*)d_in[2];
    const float* prio   = (const float*)d_in[3];
    const int*   eidx   = (const int*)  d_in[4];
    const float* np_w1  = (const float*)d_in[5];
    const float* np_b1  = (const float*)d_in[6];
    const float* bn1_g  = (const float*)d_in[7];
    const float* bn1_b  = (const float*)d_in[8];
    const float* bn1_rm = (const float*)d_in[9];
    const float* bn1_rv = (const float*)d_in[10];
    const float* np_w2  = (const float*)d_in[11];
    const float* np_b2  = (const float*)d_in[12];
    const float* bn2_g  = (const float*)d_in[13];
    const float* bn2_b  = (const float*)d_in[14];
    const float* bn2_rm = (const float*)d_in[15];
    const float* bn2_rv = (const float*)d_in[16];
    const float* np_w3  = (const float*)d_in[17];
    const float* np_b3  = (const float*)d_in[18];
    const float* ni_w   = (const float*)d_in[19];
    const float* ni_b   = (const float*)d_in[20];
    const float* ep_w1  = (const float*)d_in[21];
    const float* ep_b1  = (const float*)d_in[22];
    const float* ep_w2  = (const float*)d_in[23];
    const float* ep_b2  = (const float*)d_in[24];
    const float* ei_w   = (const float*)d_in[25];
    const float* ei_b   = (const float*)d_in[26];

    float* out = (float*)d_out;

    __nv_bfloat16 *x, *h1, *h2, *w1t, *w2t, *w3t, *ew1t, *ew2t, *ew3t;
    cudaGetSymbolAddress((void**)&x, g_x);
    cudaGetSymbolAddress((void**)&h1, g_h1);
    cudaGetSymbolAddress((void**)&h2, g_h2);
    cudaGetSymbolAddress((void**)&w1t, g_w1t);
    cudaGetSymbolAddress((void**)&w2t, g_w2t);
    cudaGetSymbolAddress((void**)&w3t, g_w3t);
    cudaGetSymbolAddress((void**)&ew1t, g_ew1t);
    cudaGetSymbolAddress((void**)&ew2t, g_ew2t);
    cudaGetSymbolAddress((void**)&ew3t, g_ew3t);

    cudaFuncSetAttribute(edge_mma_kernel,
                         cudaFuncAttributeMaxDynamicSharedMemorySize, EDGE_SMEM);
    cudaFuncSetAttribute(gemm_mma2<FDIM, H1, 1, 1>,
                         cudaFuncAttributeMaxDynamicSharedMemorySize, GEMM_SMEM);
    cudaFuncSetAttribute(gemm_mma2<H1, H2, 1, 1>,
                         cudaFuncAttributeMaxDynamicSharedMemorySize, GEMM_SMEM);
    cudaFuncSetAttribute(gemm_mma2<H2, H3, 0, 2>,
                         cudaFuncAttributeMaxDynamicSharedMemorySize, GEMM3_SMEM);

    // one-time stream/event setup (host-side resources; no device memory)
    static cudaStream_t s_edge = nullptr;
    static cudaEvent_t  ev_fork = nullptr, ev_join = nullptr;
    if (s_edge == nullptr) {
        cudaStreamCreateWithFlags(&s_edge, cudaStreamNonBlocking);
        cudaEventCreateWithFlags(&ev_fork, cudaEventDisableTiming);
        cudaEventCreateWithFlags(&ev_join, cudaEventDisableTiming);
    }

    // ---- fork immediately; side stream runs ONLY the edge branch ----
    cudaEventRecord(ev_fork, 0);
    cudaStreamWaitEvent(s_edge, ev_fork, 0);
    prep_edge_weights<<<8, 256, 0, s_edge>>>(ep_w1, ep_w2, ei_w, ew1t, ew2t, ew3t);
    edge_mma_kernel<<<NEDGE / 256, 256, EDGE_SMEM, s_edge>>>(
        bboxes, dirs, prio, eidx, ew1t, ew2t, ew3t,
        ep_b1, ep_b2, ei_b, out + NODE_OUT_ELEMS);
    cudaEventRecord(ev_join, s_edge);

    // ---- main stream: node-branch prep + GEMM chain ----
    convert_f32<<<NROWS * FDIM / 4 / 256, 256>>>((const float4*)roi, (uint2*)x);
    {
        dim3 b(32, 8);
        transpose_bf16<<<dim3(H1 / 32, FDIM / 32), b>>>(np_w1, w1t, FDIM, H1);
        transpose_bf16<<<dim3(H2 / 32, H1 / 32), b>>>(np_w2, w2t, H1, H2);
        transpose_bf16<<<dim3(H3 / 32, H2 / 32), b>>>(np_w3, w3t, H2, H3);
    }
    gemm_mma2<FDIM, H1, 1, 1><<<dim3(H1 / 128, NROWS / 128), 256, GEMM_SMEM>>>(
        x, w1t, np_b1, bn1_g, bn1_b, bn1_rm, bn1_rv,
        nullptr, nullptr, nullptr, h1);
    gemm_mma2<H1, H2, 1, 1><<<dim3(H2 / 128, NROWS / 128), 256, GEMM_SMEM>>>(
        h1, w2t, np_b2, bn2_g, bn2_b, bn2_rm, bn2_rv,
        nullptr, nullptr, nullptr, h2);
    gemm_mma2<H2, H3, 0, 2><<<dim3(H3 / 128, NROWS / 128), 256, GEMM3_SMEM>>>(
        h2, w3t, np_b3, nullptr, nullptr, nullptr, nullptr,
        ni_w, ni_b, out, nullptr);

    // join
    cudaStreamWaitEvent(0, ev_join, 0);
}

// round 14
// speedup vs baseline: 1.0231x; 1.0231x over previous
#include <cuda_runtime.h>
#include <cuda_bf16.h>
#include <cstdint>

// ---------------- problem constants (fixed by setup_inputs) ----------------
#define BATCH   32
#define NNODE   512
#define NROWS   (BATCH*NNODE)      // 16384
#define FDIM    1024
#define H1      512
#define H2      256
#define H3      128
#define NC      8
#define EDGES   32768              // per batch
#define NEDGE   (BATCH*EDGES)      // 1048576
#define EH      64
#define EC      10
#define CATTR   9
#define NODE_OUT_ELEMS (NROWS*NC)  // 131072

// ---------------- scratch (device globals; no allocation allowed) ----------
__device__ __nv_bfloat16 g_x[NROWS * FDIM];     // bf16 roi
__device__ __nv_bfloat16 g_h1[NROWS * H1];
__device__ __nv_bfloat16 g_h2[NROWS * H2];
__device__ __nv_bfloat16 g_w1t[H1 * FDIM];
__device__ __nv_bfloat16 g_w2t[H2 * H1];
__device__ __nv_bfloat16 g_w3t[H3 * H2];
__device__ __nv_bfloat16 g_ew1t[64 * 32];
__device__ __nv_bfloat16 g_ew2t[64 * 64];
__device__ __nv_bfloat16 g_ew3t[16 * 64];

// ---------------- helpers ----------------------------------------------------
__device__ __forceinline__ uint32_t smem_u32(const void* p) {
    uint32_t a;
    asm("{ .reg .u64 t; cvta.to.shared.u64 t, %1; cvt.u32.u64 %0, t; }"
        : "=r"(a) : "l"(p));
    return a;
}
__device__ __forceinline__ void ldsm4(uint32_t addr, uint32_t* r) {
    asm volatile("ldmatrix.sync.aligned.m8n8.x4.shared.b16 {%0,%1,%2,%3}, [%4];"
                 : "=r"(r[0]), "=r"(r[1]), "=r"(r[2]), "=r"(r[3]) : "r"(addr));
}
__device__ __forceinline__ void mma16816(float* c, const uint32_t* a, const uint32_t* b) {
    asm volatile(
        "mma.sync.aligned.m16n8k16.row.col.f32.bf16.bf16.f32 "
        "{%0,%1,%2,%3}, {%4,%5,%6,%7}, {%8,%9}, {%0,%1,%2,%3};"
        : "+f"(c[0]), "+f"(c[1]), "+f"(c[2]), "+f"(c[3])
        : "r"(a[0]), "r"(a[1]), "r"(a[2]), "r"(a[3]), "r"(b[0]), "r"(b[1]));
}
__device__ __forceinline__ void sts128(uint32_t addr, uint4 v) {
    asm volatile("st.shared.v4.b32 [%0], {%1,%2,%3,%4};"
                 :: "r"(addr), "r"(v.x), "r"(v.y), "r"(v.z), "r"(v.w) : "memory");
}
__device__ __forceinline__ uint32_t pack_bf2(float a, float b) {
    __nv_bfloat162 h = __floats2bfloat162_rn(a, b);
    uint32_t u; memcpy(&u, &h, 4); return u;
}
__device__ __forceinline__ void cp16(uint32_t dst, const void* src) {
    asm volatile("cp.async.cg.shared.global [%0], [%1], 16;"
                 :: "r"(dst), "l"(src) : "memory");
}
__device__ __forceinline__ void cp_commit() {
    asm volatile("cp.async.commit_group;" ::: "memory");
}
#define CP_WAIT(n) asm volatile("cp.async.wait_group %0;" :: "n"(n) : "memory")

// ---------------- single-pass bf16 mma GEMM, cp.async 3-stage pipeline ------
// K-chunk = 64 (128-byte smem rows, c^(r&7) swizzle), 3 stages.
// OMODE: 0 = fp32 out, 1 = bf16 out, 2 = fused node head.
static constexpr int STAGE_BYTES = 32768;   // A|B x 16KB (128 rows x 128B)
static constexpr int GEMM_SMEM = 3 * STAGE_BYTES;       // 96KB
static constexpr int GEMM3_SMEM = GEMM_SMEM;            // head tile 67584 < 96KB

template<int K, int N, int EPI, int OMODE>
__global__ __launch_bounds__(256)
void gemm_mma2(const __nv_bfloat16* __restrict__ A,
               const __nv_bfloat16* __restrict__ B,
               const float* __restrict__ bias,
               const float* __restrict__ bng, const float* __restrict__ bnb,
               const float* __restrict__ bnrm, const float* __restrict__ bnrv,
               const float* __restrict__ hw,  const float* __restrict__ hb,
               float* __restrict__ Cf,
               __nv_bfloat16* __restrict__ Cb)
{
    extern __shared__ char sm_raw[];
    const uint32_t sb = smem_u32(sm_raw);
    const int tid = threadIdx.x;
    const int lane = tid & 31, w = tid >> 5;
    const int bn = blockIdx.x, bm = blockIdx.y;
    const int wr = (w & 3) * 32;
    const int wc = (w >> 2) * 64;

    const __nv_bfloat16* srcs[8];
    uint32_t dsts[8];
    #pragma unroll
    for (int i = 0; i < 8; i++) {
        int idx = i * 256 + tid;
        int slab = idx >> 10;
        int within = idx & 1023;
        int r = within >> 3, c = within & 7;
        const __nv_bfloat16* base = (slab == 0) ? A : B;
        int row0 = (slab == 0) ? bm * 128 : bn * 128;
        srcs[i] = base + (size_t)(row0 + r) * K + c * 8;
        dsts[i] = slab * 16384 + r * 128 + ((c ^ (r & 7)) << 4);
    }
    auto ISSUE = [&](int ck) {
        const uint32_t st = sb + (ck % 3) * STAGE_BYTES;
        #pragma unroll
        for (int i = 0; i < 8; i++)
            cp16(st + dsts[i], srcs[i] + ck * 64);
    };

    float acc[2][8][4];
    #pragma unroll
    for (int a = 0; a < 2; a++)
        #pragma unroll
        for (int b = 0; b < 8; b++)
            #pragma unroll
            for (int c = 0; c < 4; c++) acc[a][b][c] = 0.f;

    const int m = lane >> 3, rr = lane & 7;

    auto COMPUTE = [&](int stage) {
        const uint32_t aB = sb + stage * STAGE_BYTES;
        const uint32_t bB = aB + 16384;
        #pragma unroll
        for (int ks = 0; ks < 4; ks++) {
            const int ckb = ks * 2;
            uint32_t ah[2][4], bh[4][4];
            #pragma unroll
            for (int t2 = 0; t2 < 2; t2++) {
                const int r_l = wr + t2 * 16 + ((m & 1) << 3) + rr;
                const int c_l = ckb + (m >> 1);
                const uint32_t off = r_l * 128 + ((c_l ^ (r_l & 7)) << 4);
                ldsm4(aB + off, ah[t2]);
            }
            #pragma unroll
            for (int p = 0; p < 4; p++) {
                const int n_l = wc + p * 16 + ((m >> 1) << 3) + rr;
                const int c_l = ckb + (m & 1);
                const uint32_t off = n_l * 128 + ((c_l ^ (n_l & 7)) << 4);
                ldsm4(bB + off, bh[p]);
            }
            #pragma unroll
            for (int t2 = 0; t2 < 2; t2++)
                #pragma unroll
                for (int nt = 0; nt < 8; nt++)
                    mma16816(acc[t2][nt], ah[t2], &bh[nt >> 1][(nt & 1) * 2]);
        }
    };

    constexpr int NCH = K / 64;
    ISSUE(0); cp_commit();
    ISSUE(1); cp_commit();
    for (int c = 0; c < NCH; c++) {
        CP_WAIT(1);
        __syncthreads();
        if (c + 2 < NCH) ISSUE(c + 2);
        cp_commit();
        COMPUTE(c % 3);
    }

    float* sh3 = (float*)sm_raw;
    if (OMODE == 2) __syncthreads();

    #pragma unroll
    for (int t2 = 0; t2 < 2; t2++) {
        const int rloc = wr + t2 * 16 + (lane >> 2);
        const int row0 = bm * 128 + rloc;
        #pragma unroll
        for (int nt = 0; nt < 8; nt++) {
            const int cloc = wc + nt * 8 + 2 * (lane & 3);
            const int col = bn * 128 + cloc;
            float b0 = __ldg(&bias[col]), b1 = __ldg(&bias[col + 1]);
            float s0 = 1.f, s1 = 1.f, f0 = 0.f, f1 = 0.f;
            if (EPI) {
                s0 = __ldg(&bng[col]) * rsqrtf(__ldg(&bnrv[col]) + 1e-5f);
                f0 = __ldg(&bnb[col]) - __ldg(&bnrm[col]) * s0;
                s1 = __ldg(&bng[col + 1]) * rsqrtf(__ldg(&bnrv[col + 1]) + 1e-5f);
                f1 = __ldg(&bnb[col + 1]) - __ldg(&bnrm[col + 1]) * s1;
            }
            float v00 = acc[t2][nt][0] + b0, v01 = acc[t2][nt][1] + b1;
            float v10 = acc[t2][nt][2] + b0, v11 = acc[t2][nt][3] + b1;
            if (EPI) {
                v00 = v00 * s0 + f0; v01 = v01 * s1 + f1;
                v10 = v10 * s0 + f0; v11 = v11 * s1 + f1;
            }
            v00 = fmaxf(v00, 0.f); v01 = fmaxf(v01, 0.f);
            v10 = fmaxf(v10, 0.f); v11 = fmaxf(v11, 0.f);
            if (OMODE == 1) {
                __nv_bfloat162 h0 = __floats2bfloat162_rn(v00, v01);
                __nv_bfloat162 h1 = __floats2bfloat162_rn(v10, v11);
                *(__nv_bfloat162*)(Cb + (size_t)row0 * N + col) = h0;
                *(__nv_bfloat162*)(Cb + (size_t)(row0 + 8) * N + col) = h1;
            } else if (OMODE == 2) {
                sh3[rloc * 132 + cloc]       = v00;
                sh3[rloc * 132 + cloc + 1]   = v01;
                sh3[(rloc + 8) * 132 + cloc]     = v10;
                sh3[(rloc + 8) * 132 + cloc + 1] = v11;
            } else {
                *(float2*)(Cf + (size_t)row0 * N + col) = make_float2(v00, v01);
                *(float2*)(Cf + (size_t)(row0 + 8) * N + col) = make_float2(v10, v11);
            }
        }
    }

    if (OMODE == 2) {
        __syncthreads();
        const int base = tid * 4;
        #pragma unroll
        for (int i = 0; i < 4; i++) {
            const int idx = base + i;
            const int row = idx >> 3;
            const int j = idx & 7;
            const float* xr = &sh3[row * 132];
            float a = __ldg(&hb[j]);
            #pragma unroll 8
            for (int k = 0; k < H3; k++)
                a += xr[k] * __ldg(&hw[k * NC + j]);
            Cf[(size_t)(bm * 128 + row) * NC + j] = 1.f / (1.f + __expf(-a));
        }
    }
}

// ---------------- fp32 -> bf16 convert (for roi) ----------------------------
__global__ __launch_bounds__(256)
void convert_f32(const float4* __restrict__ in, uint2* __restrict__ ob)
{
    int i = blockIdx.x * 256 + threadIdx.x;
    float4 v = in[i];
    __nv_bfloat162 h0 = __floats2bfloat162_rn(v.x, v.y);
    __nv_bfloat162 h1 = __floats2bfloat162_rn(v.z, v.w);
    uint2 u;
    memcpy(&u.x, &h0, 4); memcpy(&u.y, &h1, 4);
    ob[i] = u;
}

// ------- weight transpose to bf16 (coalesced, SMEM-tiled) -------------------
__global__ void transpose_bf16(const float* __restrict__ in,
                               __nv_bfloat16* __restrict__ ob,
                               int R, int C)
{
    __shared__ float t[32][33];
    int x = blockIdx.x * 32 + threadIdx.x;
    int y = blockIdx.y * 32 + threadIdx.y;
    #pragma unroll
    for (int i = 0; i < 32; i += 8)
        t[threadIdx.y + i][threadIdx.x] = in[(size_t)(y + i) * C + x];
    __syncthreads();
    x = blockIdx.y * 32 + threadIdx.x;
    y = blockIdx.x * 32 + threadIdx.y;
    #pragma unroll
    for (int i = 0; i < 32; i += 8)
        ob[(size_t)(y + i) * R + x] = __float2bfloat16(t[threadIdx.x][threadIdx.y + i]);
}

// ---------------- edge weight prep: transpose+pad to bf16 -------------------
// W1 k=18 slot carries b1 (bias folded into the padded K dim; A1 has x[18]=1).
__global__ void prep_edge_weights(const float* __restrict__ w1,
                                  const float* __restrict__ b1,
                                  const float* __restrict__ w2,
                                  const float* __restrict__ wi,
                                  __nv_bfloat16* __restrict__ o1,
                                  __nv_bfloat16* __restrict__ o2,
                                  __nv_bfloat16* __restrict__ o3)
{
    int t = blockIdx.x * 256 + threadIdx.x;
    int stride = gridDim.x * 256;
    for (int i = t; i < 64 * 32; i += stride) {
        int n = i >> 5, k = i & 31;
        float v = (k < 18) ? w1[k * 64 + n] : (k == 18 ? b1[n] : 0.f);
        o1[i] = __float2bfloat16(v);
    }
    for (int i = t; i < 64 * 64; i += stride) {
        int n = i >> 6, k = i & 63;
        o2[i] = __float2bfloat16(w2[k * 64 + n]);
    }
    for (int i = t; i < 16 * 64; i += stride) {
        int n = i >> 6, k = i & 63;
        o3[i] = (n < EC) ? __float2bfloat16(wi[k * EC + n]) : __nv_bfloat16(0.f);
    }
}

// ---------------- edge MLP: register-chained B2B mma ------------------------
// 256 edges / 8 warps per CTA; warp w owns rows [wrow, wrow+32).
// Layer-1 bias folded into W1 (k=18 with x[18]=1). b2/bi hoisted out of t2.
static constexpr int ESA_ATTR = 0;            // 512*10*2  = 10240
static constexpr int ESA_W1   = 10240;        //  4096
static constexpr int ESA_W2   = 14336;        //  8192
static constexpr int ESA_W3   = 22528;        //  2048
static constexpr int ESA_A1   = 24576;        // 256*64 = 16384
static constexpr int EDGE_SMEM = 40960;

__global__ __launch_bounds__(256)
void edge_mma_kernel(const float* __restrict__ bboxes,
                     const float* __restrict__ dirs,
                     const float* __restrict__ prio,
                     const int*   __restrict__ eidx,
                     const __nv_bfloat16* __restrict__ w1t,
                     const __nv_bfloat16* __restrict__ w2t,
                     const __nv_bfloat16* __restrict__ w3t,
                     const float* __restrict__ b2,
                     const float* __restrict__ bi,
                     float* __restrict__ out)
{
    extern __shared__ char sm[];
    const uint32_t sb = smem_u32(sm);
    const int tid = threadIdx.x;
    const int lane = tid & 31, w = tid >> 5;
    const int bt = blockIdx.x >> 7;
    const int e0 = (blockIdx.x & 127) * 256;

    __nv_bfloat16* sAttr = (__nv_bfloat16*)(sm + ESA_ATTR);
    const float inv = 1.f / 1024.f;
    for (int n = tid; n < NNODE; n += 256) {
        int gn = bt * NNODE + n;
        float4 bb = *(const float4*)&bboxes[(size_t)gn * 4];
        float4 dd = *(const float4*)&dirs[(size_t)gn * 4];
        float pr = prio[gn];
        __nv_bfloat16* a = sAttr + n * 10;
        a[0] = __float2bfloat16(bb.x * inv);
        a[1] = __float2bfloat16(bb.y * inv);
        a[2] = __float2bfloat16(bb.z * inv);
        a[3] = __float2bfloat16(bb.w * inv);
        a[4] = __float2bfloat16(dd.x);
        a[5] = __float2bfloat16(dd.y);
        a[6] = __float2bfloat16(dd.z);
        a[7] = __float2bfloat16(dd.w);
        a[8] = __float2bfloat16(pr);
    }
    for (int i = tid; i < 64 * 4; i += 256) {
        int r = i >> 2, c = i & 3;
        uint4 v = ((const uint4*)w1t)[r * 4 + c];
        sts128(sb + ESA_W1 + r * 64 + ((c ^ ((r >> 1) & 3)) << 4), v);
    }
    for (int i = tid; i < 64 * 8; i += 256) {
        int r = i >> 3, c = i & 7;
        uint4 v = ((const uint4*)w2t)[r * 8 + c];
        sts128(sb + ESA_W2 + r * 128 + ((c ^ (r & 7)) << 4), v);
    }
    for (int i = tid; i < 16 * 8; i += 256) {
        int r = i >> 3, c = i & 7;
        uint4 v = ((const uint4*)w3t)[r * 8 + c];
        sts128(sb + ESA_W3 + r * 128 + ((c ^ (r & 7)) << 4), v);
    }
    __syncthreads();

    // build A1: thread tid builds edge e0+tid; x[18]=1 (bias slot)
    {
        const int ebase = bt * 2 * EDGES + e0 + tid;
        const int src = eidx[ebase];
        const int dst = eidx[ebase + EDGES];
        const __nv_bfloat16* as = sAttr + src * 10;
        const __nv_bfloat16* ad = sAttr + dst * 10;
        uint16_t v[32];
        #pragma unroll
        for (int c = 0; c < 9; c++) { memcpy(&v[c], &as[c], 2); memcpy(&v[9 + c], &ad[c], 2); }
        const __nv_bfloat16 one = __float2bfloat16(1.f);
        memcpy(&v[18], &one, 2);
        #pragma unroll
        for (int c = 19; c < 32; c++) v[c] = 0;
        const int swz = (tid >> 1) & 3;
        #pragma unroll
        for (int ch = 0; ch < 4; ch++) {
            uint4 p;
            p.x = (uint32_t)v[ch*8+0] | ((uint32_t)v[ch*8+1] << 16);
            p.y = (uint32_t)v[ch*8+2] | ((uint32_t)v[ch*8+3] << 16);
            p.z = (uint32_t)v[ch*8+4] | ((uint32_t)v[ch*8+5] << 16);
            p.w = (uint32_t)v[ch*8+6] | ((uint32_t)v[ch*8+7] << 16);
            sts128(sb + ESA_A1 + tid * 64 + ((ch ^ swz) << 4), p);
        }
    }
    __syncwarp();

    const int m = lane >> 3, rr = lane & 7;
    const int wrow = (w >> 2) * 128 + (w & 3) * 32;
    const int t4 = 2 * (lane & 3);

    // ---- hoisted biases (t2-invariant) ----
    float b2A0[4], b2A1[4], b2B0[4], b2B1[4];
    #pragma unroll
    for (int kk = 0; kk < 4; kk++) {
        const int colA = 2 * kk * 8 + t4, colB = colA + 8;
        b2A0[kk] = __ldg(&b2[colA]); b2A1[kk] = __ldg(&b2[colA + 1]);
        b2B0[kk] = __ldg(&b2[colB]); b2B1[kk] = __ldg(&b2[colB + 1]);
    }
    float bi0 = 0.f, bi1 = 0.f, bi8 = 0.f, bi9 = 0.f;
    { int c0 = t4;      if (c0 < EC) { bi0 = __ldg(&bi[c0]); bi1 = __ldg(&bi[c0 + 1]); } }
    { int c8 = 8 + t4;  if (c8 < EC) { bi8 = __ldg(&bi[c8]); bi9 = __ldg(&bi[c8 + 1]); } }

    #pragma unroll
    for (int t2 = 0; t2 < 2; t2++) {
        const int rbase = wrow + t2 * 16;

        // ---- layer 1 (bias inside MMA via k=18 slot) ----
        float acc1[8][4];
        #pragma unroll
        for (int b = 0; b < 8; b++)
            #pragma unroll
            for (int c = 0; c < 4; c++) acc1[b][c] = 0.f;
        #pragma unroll
        for (int k16 = 0; k16 < 2; k16++) {
            uint32_t a[4], b[4][4];
            {
                int r = rbase + ((m & 1) << 3) + rr;
                int c = k16 * 2 + (m >> 1);
                ldsm4(sb + ESA_A1 + r * 64 + ((c ^ ((r >> 1) & 3)) << 4), a);
            }
            #pragma unroll
            for (int p = 0; p < 4; p++) {
                int n = p * 16 + ((m >> 1) << 3) + rr;
                int c = k16 * 2 + (m & 1);
                ldsm4(sb + ESA_W1 + n * 64 + ((c ^ ((n >> 1) & 3)) << 4), b[p]);
            }
            #pragma unroll
            for (int nt = 0; nt < 8; nt++)
                mma16816(acc1[nt], a, &b[nt >> 1][(nt & 1) * 2]);
        }

        // ---- relu -> layer-2 A fragments (no bias add) ----
        uint32_t a2[4][4];
        #pragma unroll
        for (int kk = 0; kk < 4; kk++) {
            const int ntA = 2 * kk, ntB = ntA + 1;
            a2[kk][0] = pack_bf2(fmaxf(acc1[ntA][0], 0.f), fmaxf(acc1[ntA][1], 0.f));
            a2[kk][1] = pack_bf2(fmaxf(acc1[ntA][2], 0.f), fmaxf(acc1[ntA][3], 0.f));
            a2[kk][2] = pack_bf2(fmaxf(acc1[ntB][0], 0.f), fmaxf(acc1[ntB][1], 0.f));
            a2[kk][3] = pack_bf2(fmaxf(acc1[ntB][2], 0.f), fmaxf(acc1[ntB][3], 0.f));
        }

        // ---- layer 2 ----
        float acc2[8][4];
        #pragma unroll
        for (int b = 0; b < 8; b++)
            #pragma unroll
            for (int c = 0; c < 4; c++) acc2[b][c] = 0.f;
        #pragma unroll
        for (int kk = 0; kk < 4; kk++) {
            uint32_t b[4][4];
            #pragma unroll
            for (int p = 0; p < 4; p++) {
                int n = p * 16 + ((m >> 1) << 3) + rr;
                int c = kk * 2 + (m & 1);
                ldsm4(sb + ESA_W2 + n * 128 + ((c ^ (n & 7)) << 4), b[p]);
            }
            #pragma unroll
            for (int nt = 0; nt < 8; nt++)
                mma16816(acc2[nt], a2[kk], &b[nt >> 1][(nt & 1) * 2]);
        }

        // ---- bias+relu -> layer-3 A fragments (hoisted biases) ----
        uint32_t a3[4][4];
        #pragma unroll
        for (int kk = 0; kk < 4; kk++) {
            const int ntA = 2 * kk, ntB = ntA + 1;
            a3[kk][0] = pack_bf2(fmaxf(acc2[ntA][0] + b2A0[kk], 0.f),
                                 fmaxf(acc2[ntA][1] + b2A1[kk], 0.f));
            a3[kk][1] = pack_bf2(fmaxf(acc2[ntA][2] + b2A0[kk], 0.f),
                                 fmaxf(acc2[ntA][3] + b2A1[kk], 0.f));
            a3[kk][2] = pack_bf2(fmaxf(acc2[ntB][0] + b2B0[kk], 0.f),
                                 fmaxf(acc2[ntB][1] + b2B1[kk], 0.f));
            a3[kk][3] = pack_bf2(fmaxf(acc2[ntB][2] + b2B0[kk], 0.f),
                                 fmaxf(acc2[ntB][3] + b2B1[kk], 0.f));
        }

        // ---- layer 3 ----
        float acc3[2][4];
        #pragma unroll
        for (int b = 0; b < 2; b++)
            #pragma unroll
            for (int c = 0; c < 4; c++) acc3[b][c] = 0.f;
        #pragma unroll
        for (int kk = 0; kk < 4; kk++) {
            uint32_t b[4];
            int n = ((m >> 1) << 3) + rr;
            int c = kk * 2 + (m & 1);
            ldsm4(sb + ESA_W3 + n * 128 + ((c ^ (n & 7)) << 4), b);
            mma16816(acc3[0], a3[kk], &b[0]);
            mma16816(acc3[1], a3[kk], &b[2]);
        }

        // ---- sigmoid + store ----
        const int r0 = rbase + (lane >> 2);
        const long eg = (long)bt * EDGES + e0 + r0;
        if (t4 < EC) {       // nt = 0 always valid (cols 0..7)
            float s00 = 1.f / (1.f + __expf(-(acc3[0][0] + bi0)));
            float s01 = 1.f / (1.f + __expf(-(acc3[0][1] + bi1)));
            float s10 = 1.f / (1.f + __expf(-(acc3[0][2] + bi0)));
            float s11 = 1.f / (1.f + __expf(-(acc3[0][3] + bi1)));
            *(float2*)(out + eg * EC + t4) = make_float2(s00, s01);
            *(float2*)(out + (eg + 8) * EC + t4) = make_float2(s10, s11);
        }
        if (8 + t4 < EC) {   // nt = 1 (cols 8..9)
            float s00 = 1.f / (1.f + __expf(-(acc3[1][0] + bi8)));
            float s01 = 1.f / (1.f + __expf(-(acc3[1][1] + bi9)));
            float s10 = 1.f / (1.f + __expf(-(acc3[1][2] + bi8)));
            float s11 = 1.f / (1.f + __expf(-(acc3[1][3] + bi9)));
            *(float2*)(out + eg * EC + 8 + t4) = make_float2(s00, s01);
            *(float2*)(out + (eg + 8) * EC + 8 + t4) = make_float2(s10, s11);
        }
    }
}

// ---------------- launch ----------------------------------------------------
extern "C" void kernel_launch(void* const* d_in, const int* in_sizes, int n_in,
                              void* d_out, int out_size)
{
    const float* roi    = (const float*)d_in[0];
    const float* bboxes = (const float*)d_in[1];
    const float* dirs   = (const float*)d_in[2];
    const float* prio   = (const float*)d_in[3];
    const int*   eidx   = (const int*)  d_in[4];
    const float* np_w1  = (const float*)d_in[5];
    const float* np_b1  = (const float*)d_in[6];
    const float* bn1_g  = (const float*)d_in[7];
    const float* bn1_b  = (const float*)d_in[8];
    const float* bn1_rm = (const float*)d_in[9];
    const float* bn1_rv = (const float*)d_in[10];
    const float* np_w2  = (const float*)d_in[11];
    const float* np_b2  = (const float*)d_in[12];
    const float* bn2_g  = (const float*)d_in[13];
    const float* bn2_b  = (const float*)d_in[14];
    const float* bn2_rm = (const float*)d_in[15];
    const float* bn2_rv = (const float*)d_in[16];
    const float* np_w3  = (const float*)d_in[17];
    const float* np_b3  = (const float*)d_in[18];
    const float* ni_w   = (const float*)d_in[19];
    const float* ni_b   = (const float*)d_in[20];
    const float* ep_w1  = (const float*)d_in[21];
    const float* ep_b1  = (const float*)d_in[22];
    const float* ep_w2  = (const float*)d_in[23];
    const float* ep_b2  = (const float*)d_in[24];
    const float* ei_w   = (const float*)d_in[25];
    const float* ei_b   = (const float*)d_in[26];

    float* out = (float*)d_out;

    __nv_bfloat16 *x, *h1, *h2, *w1t, *w2t, *w3t, *ew1t, *ew2t, *ew3t;
    cudaGetSymbolAddress((void**)&x, g_x);
    cudaGetSymbolAddress((void**)&h1, g_h1);
    cudaGetSymbolAddress((void**)&h2, g_h2);
    cudaGetSymbolAddress((void**)&w1t, g_w1t);
    cudaGetSymbolAddress((void**)&w2t, g_w2t);
    cudaGetSymbolAddress((void**)&w3t, g_w3t);
    cudaGetSymbolAddress((void**)&ew1t, g_ew1t);
    cudaGetSymbolAddress((void**)&ew2t, g_ew2t);
    cudaGetSymbolAddress((void**)&ew3t, g_ew3t);

    cudaFuncSetAttribute(edge_mma_kernel,
                         cudaFuncAttributeMaxDynamicSharedMemorySize, EDGE_SMEM);
    cudaFuncSetAttribute(gemm_mma2<FDIM, H1, 1, 1>,
                         cudaFuncAttributeMaxDynamicSharedMemorySize, GEMM_SMEM);
    cudaFuncSetAttribute(gemm_mma2<H1, H2, 1, 1>,
                         cudaFuncAttributeMaxDynamicSharedMemorySize, GEMM_SMEM);
    cudaFuncSetAttribute(gemm_mma2<H2, H3, 0, 2>,
                         cudaFuncAttributeMaxDynamicSharedMemorySize, GEMM3_SMEM);

    // one-time stream/event setup (host-side resources; no device memory)
    static cudaStream_t s_edge = nullptr;
    static cudaEvent_t  ev_fork = nullptr, ev_w = nullptr, ev_join = nullptr;
    if (s_edge == nullptr) {
        cudaStreamCreateWithFlags(&s_edge, cudaStreamNonBlocking);
        cudaEventCreateWithFlags(&ev_fork, cudaEventDisableTiming);
        cudaEventCreateWithFlags(&ev_w, cudaEventDisableTiming);
        cudaEventCreateWithFlags(&ev_join, cudaEventDisableTiming);
    }

    // ---- R12 schedule: side stream = transposes -> edge prep -> edges ----
    cudaEventRecord(ev_fork, 0);
    cudaStreamWaitEvent(s_edge, ev_fork, 0);

    // main stream: roi convert (critical path for GEMM1's A operand)
    convert_f32<<<NROWS * FDIM / 4 / 256, 256>>>((const float4*)roi, (uint2*)x);

    // side stream: node-weight transposes, then edge prep + edge kernel
    {
        dim3 b(32, 8);
        transpose_bf16<<<dim3(H1 / 32, FDIM / 32), b, 0, s_edge>>>(np_w1, w1t, FDIM, H1);
        transpose_bf16<<<dim3(H2 / 32, H1 / 32), b, 0, s_edge>>>(np_w2, w2t, H1, H2);
        transpose_bf16<<<dim3(H3 / 32, H2 / 32), b, 0, s_edge>>>(np_w3, w3t, H2, H3);
    }
    cudaEventRecord(ev_w, s_edge);
    prep_edge_weights<<<8, 256, 0, s_edge>>>(ep_w1, ep_b1, ep_w2, ei_w,
                                             ew1t, ew2t, ew3t);
    edge_mma_kernel<<<NEDGE / 256, 256, EDGE_SMEM, s_edge>>>(
        bboxes, dirs, prio, eidx, ew1t, ew2t, ew3t,
        ep_b2, ei_b, out + NODE_OUT_ELEMS);
    cudaEventRecord(ev_join, s_edge);

    // main stream: node GEMM chain (needs transposed weights)
    cudaStreamWaitEvent(0, ev_w, 0);
    gemm_mma2<FDIM, H1, 1, 1><<<dim3(H1 / 128, NROWS / 128), 256, GEMM_SMEM>>>(
        x, w1t, np_b1, bn1_g, bn1_b, bn1_rm, bn1_rv,
        nullptr, nullptr, nullptr, h1);
    gemm_mma2<H1, H2, 1, 1><<<dim3(H2 / 128, NROWS / 128), 256, GEMM_SMEM>>>(
        h1, w2t, np_b2, bn2_g, bn2_b, bn2_rm, bn2_rv,
        nullptr, nullptr, nullptr, h2);
    gemm_mma2<H2, H3, 0, 2><<<dim3(H3 / 128, NROWS / 128), 256, GEMM3_SMEM>>>(
        h2, w3t, np_b3, nullptr, nullptr, nullptr, nullptr,
        ni_w, ni_b, out, nullptr);

    // join
    cudaStreamWaitEvent(0, ev_join, 0);
}

// round 16
// speedup vs baseline: 1.0730x; 1.0488x over previous
#include <cuda_runtime.h>
#include <cuda_bf16.h>
#include <cstdint>

// ---------------- problem constants (fixed by setup_inputs) ----------------
#define BATCH   32
#define NNODE   512
#define NROWS   (BATCH*NNODE)      // 16384
#define FDIM    1024
#define H1      512
#define H2      256
#define H3      128
#define NC      8
#define EDGES   32768              // per batch
#define NEDGE   (BATCH*EDGES)      // 1048576
#define EH      64
#define EC      10
#define CATTR   9
#define NODE_OUT_ELEMS (NROWS*NC)  // 131072

// ---------------- scratch (device globals; no allocation allowed) ----------
__device__ __nv_bfloat16 g_x[NROWS * FDIM];     // bf16 roi
__device__ __nv_bfloat16 g_h1[NROWS * H1];
__device__ __nv_bfloat16 g_h2[NROWS * H2];
__device__ __nv_bfloat16 g_w1t[H1 * FDIM];
__device__ __nv_bfloat16 g_w2t[H2 * H1];
__device__ __nv_bfloat16 g_w3t[H3 * H2];
__device__ __nv_bfloat16 g_ew1t[64 * 32];
__device__ __nv_bfloat16 g_ew2t[64 * 64];
__device__ __nv_bfloat16 g_ew3t[16 * 64];
__device__ __nv_bfloat16 g_attr[BATCH * NNODE * 10];   // precomputed node attrs

// ---------------- helpers ----------------------------------------------------
__device__ __forceinline__ uint32_t smem_u32(const void* p) {
    uint32_t a;
    asm("{ .reg .u64 t; cvta.to.shared.u64 t, %1; cvt.u32.u64 %0, t; }"
        : "=r"(a) : "l"(p));
    return a;
}
__device__ __forceinline__ void ldsm4(uint32_t addr, uint32_t* r) {
    asm volatile("ldmatrix.sync.aligned.m8n8.x4.shared.b16 {%0,%1,%2,%3}, [%4];"
                 : "=r"(r[0]), "=r"(r[1]), "=r"(r[2]), "=r"(r[3]) : "r"(addr));
}
__device__ __forceinline__ void mma16816(float* c, const uint32_t* a, const uint32_t* b) {
    asm volatile(
        "mma.sync.aligned.m16n8k16.row.col.f32.bf16.bf16.f32 "
        "{%0,%1,%2,%3}, {%4,%5,%6,%7}, {%8,%9}, {%0,%1,%2,%3};"
        : "+f"(c[0]), "+f"(c[1]), "+f"(c[2]), "+f"(c[3])
        : "r"(a[0]), "r"(a[1]), "r"(a[2]), "r"(a[3]), "r"(b[0]), "r"(b[1]));
}
__device__ __forceinline__ void sts128(uint32_t addr, uint4 v) {
    asm volatile("st.shared.v4.b32 [%0], {%1,%2,%3,%4};"
                 :: "r"(addr), "r"(v.x), "r"(v.y), "r"(v.z), "r"(v.w) : "memory");
}
__device__ __forceinline__ void sts32(uint32_t addr, uint32_t v) {
    asm volatile("st.shared.b32 [%0], %1;" :: "r"(addr), "r"(v) : "memory");
}
__device__ __forceinline__ uint32_t pack_bf2(float a, float b) {
    __nv_bfloat162 h = __floats2bfloat162_rn(a, b);
    uint32_t u; memcpy(&u, &h, 4); return u;
}
__device__ __forceinline__ void cp16(uint32_t dst, const void* src) {
    asm volatile("cp.async.cg.shared.global [%0], [%1], 16;"
                 :: "r"(dst), "l"(src) : "memory");
}
__device__ __forceinline__ void cp_commit() {
    asm volatile("cp.async.commit_group;" ::: "memory");
}
#define CP_WAIT(n) asm volatile("cp.async.wait_group %0;" :: "n"(n) : "memory")

// ---------------- single-pass bf16 mma GEMM, cp.async 3-stage pipeline ------
// K-chunk = 64 (128-byte smem rows, c^(r&7) swizzle), 3 stages.  (R12 exact)
static constexpr int STAGE_BYTES = 32768;
static constexpr int GEMM_SMEM = 3 * STAGE_BYTES;
static constexpr int GEMM3_SMEM = GEMM_SMEM;

template<int K, int N, int EPI, int OMODE>
__global__ __launch_bounds__(256)
void gemm_mma2(const __nv_bfloat16* __restrict__ A,
               const __nv_bfloat16* __restrict__ B,
               const float* __restrict__ bias,
               const float* __restrict__ bng, const float* __restrict__ bnb,
               const float* __restrict__ bnrm, const float* __restrict__ bnrv,
               const float* __restrict__ hw,  const float* __restrict__ hb,
               float* __restrict__ Cf,
               __nv_bfloat16* __restrict__ Cb)
{
    extern __shared__ char sm_raw[];
    const uint32_t sb = smem_u32(sm_raw);
    const int tid = threadIdx.x;
    const int lane = tid & 31, w = tid >> 5;
    const int bn = blockIdx.x, bm = blockIdx.y;
    const int wr = (w & 3) * 32;
    const int wc = (w >> 2) * 64;

    const __nv_bfloat16* srcs[8];
    uint32_t dsts[8];
    #pragma unroll
    for (int i = 0; i < 8; i++) {
        int idx = i * 256 + tid;
        int slab = idx >> 10;
        int within = idx & 1023;
        int r = within >> 3, c = within & 7;
        const __nv_bfloat16* base = (slab == 0) ? A : B;
        int row0 = (slab == 0) ? bm * 128 : bn * 128;
        srcs[i] = base + (size_t)(row0 + r) * K + c * 8;
        dsts[i] = slab * 16384 + r * 128 + ((c ^ (r & 7)) << 4);
    }
    auto ISSUE = [&](int ck) {
        const uint32_t st = sb + (ck % 3) * STAGE_BYTES;
        #pragma unroll
        for (int i = 0; i < 8; i++)
            cp16(st + dsts[i], srcs[i] + ck * 64);
    };

    float acc[2][8][4];
    #pragma unroll
    for (int a = 0; a < 2; a++)
        #pragma unroll
        for (int b = 0; b < 8; b++)
            #pragma unroll
            for (int c = 0; c < 4; c++) acc[a][b][c] = 0.f;

    const int m = lane >> 3, rr = lane & 7;

    auto COMPUTE = [&](int stage) {
        const uint32_t aB = sb + stage * STAGE_BYTES;
        const uint32_t bB = aB + 16384;
        #pragma unroll
        for (int ks = 0; ks < 4; ks++) {
            const int ckb = ks * 2;
            uint32_t ah[2][4], bh[4][4];
            #pragma unroll
            for (int t2 = 0; t2 < 2; t2++) {
                const int r_l = wr + t2 * 16 + ((m & 1) << 3) + rr;
                const int c_l = ckb + (m >> 1);
                const uint32_t off = r_l * 128 + ((c_l ^ (r_l & 7)) << 4);
                ldsm4(aB + off, ah[t2]);
            }
            #pragma unroll
            for (int p = 0; p < 4; p++) {
                const int n_l = wc + p * 16 + ((m >> 1) << 3) + rr;
                const int c_l = ckb + (m & 1);
                const uint32_t off = n_l * 128 + ((c_l ^ (n_l & 7)) << 4);
                ldsm4(bB + off, bh[p]);
            }
            #pragma unroll
            for (int t2 = 0; t2 < 2; t2++)
                #pragma unroll
                for (int nt = 0; nt < 8; nt++)
                    mma16816(acc[t2][nt], ah[t2], &bh[nt >> 1][(nt & 1) * 2]);
        }
    };

    constexpr int NCH = K / 64;
    ISSUE(0); cp_commit();
    ISSUE(1); cp_commit();
    for (int c = 0; c < NCH; c++) {
        CP_WAIT(1);
        __syncthreads();
        if (c + 2 < NCH) ISSUE(c + 2);
        cp_commit();
        COMPUTE(c % 3);
    }

    float* sh3 = (float*)sm_raw;
    if (OMODE == 2) __syncthreads();

    #pragma unroll
    for (int t2 = 0; t2 < 2; t2++) {
        const int rloc = wr + t2 * 16 + (lane >> 2);
        const int row0 = bm * 128 + rloc;
        #pragma unroll
        for (int nt = 0; nt < 8; nt++) {
            const int cloc = wc + nt * 8 + 2 * (lane & 3);
            const int col = bn * 128 + cloc;
            float b0 = __ldg(&bias[col]), b1 = __ldg(&bias[col + 1]);
            float s0 = 1.f, s1 = 1.f, f0 = 0.f, f1 = 0.f;
            if (EPI) {
                s0 = __ldg(&bng[col]) * rsqrtf(__ldg(&bnrv[col]) + 1e-5f);
                f0 = __ldg(&bnb[col]) - __ldg(&bnrm[col]) * s0;
                s1 = __ldg(&bng[col + 1]) * rsqrtf(__ldg(&bnrv[col + 1]) + 1e-5f);
                f1 = __ldg(&bnb[col + 1]) - __ldg(&bnrm[col + 1]) * s1;
            }
            float v00 = acc[t2][nt][0] + b0, v01 = acc[t2][nt][1] + b1;
            float v10 = acc[t2][nt][2] + b0, v11 = acc[t2][nt][3] + b1;
            if (EPI) {
                v00 = v00 * s0 + f0; v01 = v01 * s1 + f1;
                v10 = v10 * s0 + f0; v11 = v11 * s1 + f1;
            }
            v00 = fmaxf(v00, 0.f); v01 = fmaxf(v01, 0.f);
            v10 = fmaxf(v10, 0.f); v11 = fmaxf(v11, 0.f);
            if (OMODE == 1) {
                __nv_bfloat162 h0 = __floats2bfloat162_rn(v00, v01);
                __nv_bfloat162 h1 = __floats2bfloat162_rn(v10, v11);
                *(__nv_bfloat162*)(Cb + (size_t)row0 * N + col) = h0;
                *(__nv_bfloat162*)(Cb + (size_t)(row0 + 8) * N + col) = h1;
            } else if (OMODE == 2) {
                sh3[rloc * 132 + cloc]       = v00;
                sh3[rloc * 132 + cloc + 1]   = v01;
                sh3[(rloc + 8) * 132 + cloc]     = v10;
                sh3[(rloc + 8) * 132 + cloc + 1] = v11;
            } else {
                *(float2*)(Cf + (size_t)row0 * N + col) = make_float2(v00, v01);
                *(float2*)(Cf + (size_t)(row0 + 8) * N + col) = make_float2(v10, v11);
            }
        }
    }

    if (OMODE == 2) {
        __syncthreads();
        const int base = tid * 4;
        #pragma unroll
        for (int i = 0; i < 4; i++) {
            const int idx = base + i;
            const int row = idx >> 3;
            const int j = idx & 7;
            const float* xr = &sh3[row * 132];
            float a = __ldg(&hb[j]);
            #pragma unroll 8
            for (int k = 0; k < H3; k++)
                a += xr[k] * __ldg(&hw[k * NC + j]);
            Cf[(size_t)(bm * 128 + row) * NC + j] = 1.f / (1.f + __expf(-a));
        }
    }
}

// ---------------- fp32 -> bf16 convert (for roi) ----------------------------
__global__ __launch_bounds__(256)
void convert_f32(const float4* __restrict__ in, uint2* __restrict__ ob)
{
    int i = blockIdx.x * 256 + threadIdx.x;
    float4 v = in[i];
    __nv_bfloat162 h0 = __floats2bfloat162_rn(v.x, v.y);
    __nv_bfloat162 h1 = __floats2bfloat162_rn(v.z, v.w);
    uint2 u;
    memcpy(&u.x, &h0, 4); memcpy(&u.y, &h1, 4);
    ob[i] = u;
}

// ------- fused 3-matrix transpose to bf16 (one launch, coalesced) -----------
__global__ void transpose3(const float* __restrict__ w1,
                           const float* __restrict__ w2,
                           const float* __restrict__ w3,
                           __nv_bfloat16* __restrict__ o1,
                           __nv_bfloat16* __restrict__ o2,
                           __nv_bfloat16* __restrict__ o3)
{
    __shared__ float t[32][33];
    const int z = blockIdx.z;
    const float* in; __nv_bfloat16* ob; int R, C, gx, gy;
    if (z == 0)      { in = w1; ob = o1; R = FDIM; C = H1; gx = H1/32; gy = FDIM/32; }
    else if (z == 1) { in = w2; ob = o2; R = H1;   C = H2; gx = H2/32; gy = H1/32; }
    else             { in = w3; ob = o3; R = H2;   C = H3; gx = H3/32; gy = H2/32; }
    if ((int)blockIdx.x >= gx || (int)blockIdx.y >= gy) return;

    int x = blockIdx.x * 32 + threadIdx.x;
    int y = blockIdx.y * 32 + threadIdx.y;
    #pragma unroll
    for (int i = 0; i < 32; i += 8)
        t[threadIdx.y + i][threadIdx.x] = in[(size_t)(y + i) * C + x];
    __syncthreads();
    x = blockIdx.y * 32 + threadIdx.x;
    y = blockIdx.x * 32 + threadIdx.y;
    #pragma unroll
    for (int i = 0; i < 32; i += 8)
        ob[(size_t)(y + i) * R + x] = __float2bfloat16(t[threadIdx.x][threadIdx.y + i]);
}

// ------- edge prep: weights (transpose+pad bf16) + node attr table ----------
__global__ __launch_bounds__(256)
void prep_edge(const float* __restrict__ w1, const float* __restrict__ w2,
               const float* __restrict__ wi,
               const float* __restrict__ bboxes, const float* __restrict__ dirs,
               const float* __restrict__ prio,
               __nv_bfloat16* __restrict__ o1, __nv_bfloat16* __restrict__ o2,
               __nv_bfloat16* __restrict__ o3, __nv_bfloat16* __restrict__ attr)
{
    const int t = blockIdx.x * 256 + threadIdx.x;
    const int S = gridDim.x * 256;
    for (int i = t; i < 64 * 32; i += S) {
        int n = i >> 5, k = i & 31;
        o1[i] = (k < 18) ? __float2bfloat16(w1[k * 64 + n]) : __nv_bfloat16(0.f);
    }
    for (int i = t; i < 64 * 64; i += S) {
        int n = i >> 6, k = i & 63;
        o2[i] = __float2bfloat16(w2[k * 64 + n]);
    }
    for (int i = t; i < 16 * 64; i += S) {
        int n = i >> 6, k = i & 63;
        o3[i] = (n < EC) ? __float2bfloat16(wi[k * EC + n]) : __nv_bfloat16(0.f);
    }
    // node attrs (identical math to the old per-CTA staging)
    const float inv = 1.f / 1024.f;
    for (int gn = t; gn < BATCH * NNODE; gn += S) {
        float4 bb = *(const float4*)&bboxes[(size_t)gn * 4];
        float4 dd = *(const float4*)&dirs[(size_t)gn * 4];
        float pr = prio[gn];
        __nv_bfloat16* a = attr + (size_t)gn * 10;
        a[0] = __float2bfloat16(bb.x * inv);
        a[1] = __float2bfloat16(bb.y * inv);
        a[2] = __float2bfloat16(bb.z * inv);
        a[3] = __float2bfloat16(bb.w * inv);
        a[4] = __float2bfloat16(dd.x);
        a[5] = __float2bfloat16(dd.y);
        a[6] = __float2bfloat16(dd.z);
        a[7] = __float2bfloat16(dd.w);
        a[8] = __float2bfloat16(pr);
        a[9] = __nv_bfloat16(0.f);
    }
}

// ---------------- edge MLP: register-chained B2B mma (R12 math core) --------
static constexpr int ESA_ATTR = 0;            // 512*10*2  = 10240
static constexpr int ESA_W1   = 10240;
static constexpr int ESA_W2   = 14336;
static constexpr int ESA_W3   = 22528;
static constexpr int ESA_A1   = 24576;        // 256*64 = 16384
static constexpr int EDGE_SMEM = 40960;

__global__ __launch_bounds__(256)
void edge_mma_kernel(const __nv_bfloat16* __restrict__ attr,
                     const int*   __restrict__ eidx,
                     const __nv_bfloat16* __restrict__ w1t,
                     const __nv_bfloat16* __restrict__ w2t,
                     const __nv_bfloat16* __restrict__ w3t,
                     const float* __restrict__ b1,
                     const float* __restrict__ b2,
                     const float* __restrict__ bi,
                     float* __restrict__ out)
{
    extern __shared__ char sm[];
    const uint32_t sb = smem_u32(sm);
    const int tid = threadIdx.x;
    const int lane = tid & 31, w = tid >> 5;
    const int bt = blockIdx.x >> 7;
    const int e0 = (blockIdx.x & 127) * 256;

    // stage precomputed attr table: raw 16B copy (10240 B)
    {
        const uint4* asrc = (const uint4*)(attr + (size_t)bt * NNODE * 10);
        for (int i = tid; i < NNODE * 10 * 2 / 16; i += 256)
            sts128(sb + ESA_ATTR + i * 16, asrc[i]);
    }
    for (int i = tid; i < 64 * 4; i += 256) {
        int r = i >> 2, c = i & 3;
        uint4 v = ((const uint4*)w1t)[r * 4 + c];
        sts128(sb + ESA_W1 + r * 64 + ((c ^ ((r >> 1) & 3)) << 4), v);
    }
    for (int i = tid; i < 64 * 8; i += 256) {
        int r = i >> 3, c = i & 7;
        uint4 v = ((const uint4*)w2t)[r * 8 + c];
        sts128(sb + ESA_W2 + r * 128 + ((c ^ (r & 7)) << 4), v);
    }
    for (int i = tid; i < 16 * 8; i += 256) {
        int r = i >> 3, c = i & 7;
        uint4 v = ((const uint4*)w3t)[r * 8 + c];
        sts128(sb + ESA_W3 + r * 128 + ((c ^ (r & 7)) << 4), v);
    }
    __syncthreads();

    __nv_bfloat16* sAttr = (__nv_bfloat16*)(sm + ESA_ATTR);
    {
        const int ebase = bt * 2 * EDGES + e0 + tid;
        const int src = eidx[ebase];
        const int dst = eidx[ebase + EDGES];
        const __nv_bfloat16* as = sAttr + src * 10;
        const __nv_bfloat16* ad = sAttr + dst * 10;
        uint16_t v[32];
        #pragma unroll
        for (int c = 0; c < 9; c++) { memcpy(&v[c], &as[c], 2); memcpy(&v[9 + c], &ad[c], 2); }
        #pragma unroll
        for (int c = 18; c < 32; c++) v[c] = 0;
        const int swz = (tid >> 1) & 3;
        #pragma unroll
        for (int ch = 0; ch < 4; ch++) {
            uint4 p;
            p.x = (uint32_t)v[ch*8+0] | ((uint32_t)v[ch*8+1] << 16);
            p.y = (uint32_t)v[ch*8+2] | ((uint32_t)v[ch*8+3] << 16);
            p.z = (uint32_t)v[ch*8+4] | ((uint32_t)v[ch*8+5] << 16);
            p.w = (uint32_t)v[ch*8+6] | ((uint32_t)v[ch*8+7] << 16);
            sts128(sb + ESA_A1 + tid * 64 + ((ch ^ swz) << 4), p);
        }
    }
    __syncwarp();

    const int m = lane >> 3, rr = lane & 7;
    const int wrow = (w >> 2) * 128 + (w & 3) * 32;
    const int t4 = 2 * (lane & 3);

    #pragma unroll
    for (int t2 = 0; t2 < 2; t2++) {
        const int rbase = wrow + t2 * 16;

        float acc1[8][4];
        #pragma unroll
        for (int b = 0; b < 8; b++)
            #pragma unroll
            for (int c = 0; c < 4; c++) acc1[b][c] = 0.f;
        #pragma unroll
        for (int k16 = 0; k16 < 2; k16++) {
            uint32_t a[4], b[4][4];
            {
                int r = rbase + ((m & 1) << 3) + rr;
                int c = k16 * 2 + (m >> 1);
                ldsm4(sb + ESA_A1 + r * 64 + ((c ^ ((r >> 1) & 3)) << 4), a);
            }
            #pragma unroll
            for (int p = 0; p < 4; p++) {
                int n = p * 16 + ((m >> 1) << 3) + rr;
                int c = k16 * 2 + (m & 1);
                ldsm4(sb + ESA_W1 + n * 64 + ((c ^ ((n >> 1) & 3)) << 4), b[p]);
            }
            #pragma unroll
            for (int nt = 0; nt < 8; nt++)
                mma16816(acc1[nt], a, &b[nt >> 1][(nt & 1) * 2]);
        }

        uint32_t a2[4][4];
        #pragma unroll
        for (int kk = 0; kk < 4; kk++) {
            const int ntA = 2 * kk, ntB = ntA + 1;
            const int colA = ntA * 8 + t4, colB = ntB * 8 + t4;
            float bA0 = __ldg(&b1[colA]), bA1 = __ldg(&b1[colA + 1]);
            float bB0 = __ldg(&b1[colB]), bB1 = __ldg(&b1[colB + 1]);
            a2[kk][0] = pack_bf2(fmaxf(acc1[ntA][0] + bA0, 0.f),
                                 fmaxf(acc1[ntA][1] + bA1, 0.f));
            a2[kk][1] = pack_bf2(fmaxf(acc1[ntA][2] + bA0, 0.f),
                                 fmaxf(acc1[ntA][3] + bA1, 0.f));
            a2[kk][2] = pack_bf2(fmaxf(acc1[ntB][0] + bB0, 0.f),
                                 fmaxf(acc1[ntB][1] + bB1, 0.f));
            a2[kk][3] = pack_bf2(fmaxf(acc1[ntB][2] + bB0, 0.f),
                                 fmaxf(acc1[ntB][3] + bB1, 0.f));
        }

        float acc2[8][4];
        #pragma unroll
        for (int b = 0; b < 8; b++)
            #pragma unroll
            for (int c = 0; c < 4; c++) acc2[b][c] = 0.f;
        #pragma unroll
        for (int kk = 0; kk < 4; kk++) {
            uint32_t b[4][4];
            #pragma unroll
            for (int p = 0; p < 4; p++) {
                int n = p * 16 + ((m >> 1) << 3) + rr;
                int c = kk * 2 + (m & 1);
                ldsm4(sb + ESA_W2 + n * 128 + ((c ^ (n & 7)) << 4), b[p]);
            }
            #pragma unroll
            for (int nt = 0; nt < 8; nt++)
                mma16816(acc2[nt], a2[kk], &b[nt >> 1][(nt & 1) * 2]);
        }

        uint32_t a3[4][4];
        #pragma unroll
        for (int kk = 0; kk < 4; kk++) {
            const int ntA = 2 * kk, ntB = ntA + 1;
            const int colA = ntA * 8 + t4, colB = ntB * 8 + t4;
            float bA0 = __ldg(&b2[colA]), bA1 = __ldg(&b2[colA + 1]);
            float bB0 = __ldg(&b2[colB]), bB1 = __ldg(&b2[colB + 1]);
            a3[kk][0] = pack_bf2(fmaxf(acc2[ntA][0] + bA0, 0.f),
                                 fmaxf(acc2[ntA][1] + bA1, 0.f));
            a3[kk][1] = pack_bf2(fmaxf(acc2[ntA][2] + bA0, 0.f),
                                 fmaxf(acc2[ntA][3] + bA1, 0.f));
            a3[kk][2] = pack_bf2(fmaxf(acc2[ntB][0] + bB0, 0.f),
                                 fmaxf(acc2[ntB][1] + bB1, 0.f));
            a3[kk][3] = pack_bf2(fmaxf(acc2[ntB][2] + bB0, 0.f),
                                 fmaxf(acc2[ntB][3] + bB1, 0.f));
        }

        float acc3[2][4];
        #pragma unroll
        for (int b = 0; b < 2; b++)
            #pragma unroll
            for (int c = 0; c < 4; c++) acc3[b][c] = 0.f;
        #pragma unroll
        for (int kk = 0; kk < 4; kk++) {
            uint32_t b[4];
            int n = ((m >> 1) << 3) + rr;
            int c = kk * 2 + (m & 1);
            ldsm4(sb + ESA_W3 + n * 128 + ((c ^ (n & 7)) << 4), b);
            mma16816(acc3[0], a3[kk], &b[0]);
            mma16816(acc3[1], a3[kk], &b[2]);
        }

        const int r0 = rbase + (lane >> 2);
        const long eg = (long)bt * EDGES + e0 + r0;
        #pragma unroll
        for (int nt = 0; nt < 2; nt++) {
            const int col = nt * 8 + t4;
            if (col < EC) {
                float bb0 = __ldg(&bi[col]), bb1 = __ldg(&bi[col + 1]);
                float s00 = 1.f / (1.f + __expf(-(acc3[nt][0] + bb0)));
                float s01 = 1.f / (1.f + __expf(-(acc3[nt][1] + bb1)));
                float s10 = 1.f / (1.f + __expf(-(acc3[nt][2] + bb0)));
                float s11 = 1.f / (1.f + __expf(-(acc3[nt][3] + bb1)));
                *(float2*)(out + eg * EC + col) = make_float2(s00, s01);
                *(float2*)(out + (eg + 8) * EC + col) = make_float2(s10, s11);
            }
        }
    }
}

// ---------------- launch ----------------------------------------------------
extern "C" void kernel_launch(void* const* d_in, const int* in_sizes, int n_in,
                              void* d_out, int out_size)
{
    const float* roi    = (const float*)d_in[0];
    const float* bboxes = (const float*)d_in[1];
    const float* dirs   = (const float*)d_in[2];
    const float* prio   = (const float*)d_in[3];
    const int*   eidx   = (const int*)  d_in[4];
    const float* np_w1  = (const float*)d_in[5];
    const float* np_b1  = (const float*)d_in[6];
    const float* bn1_g  = (const float*)d_in[7];
    const float* bn1_b  = (const float*)d_in[8];
    const float* bn1_rm = (const float*)d_in[9];
    const float* bn1_rv = (const float*)d_in[10];
    const float* np_w2  = (const float*)d_in[11];
    const float* np_b2  = (const float*)d_in[12];
    const float* bn2_g  = (const float*)d_in[13];
    const float* bn2_b  = (const float*)d_in[14];
    const float* bn2_rm = (const float*)d_in[15];
    const float* bn2_rv = (const float*)d_in[16];
    const float* np_w3  = (const float*)d_in[17];
    const float* np_b3  = (const float*)d_in[18];
    const float* ni_w   = (const float*)d_in[19];
    const float* ni_b   = (const float*)d_in[20];
    const float* ep_w1  = (const float*)d_in[21];
    const float* ep_b1  = (const float*)d_in[22];
    const float* ep_w2  = (const float*)d_in[23];
    const float* ep_b2  = (const float*)d_in[24];
    const float* ei_w   = (const float*)d_in[25];
    const float* ei_b   = (const float*)d_in[26];

    float* out = (float*)d_out;

    __nv_bfloat16 *x, *h1, *h2, *w1t, *w2t, *w3t, *ew1t, *ew2t, *ew3t, *attr;
    cudaGetSymbolAddress((void**)&x, g_x);
    cudaGetSymbolAddress((void**)&h1, g_h1);
    cudaGetSymbolAddress((void**)&h2, g_h2);
    cudaGetSymbolAddress((void**)&w1t, g_w1t);
    cudaGetSymbolAddress((void**)&w2t, g_w2t);
    cudaGetSymbolAddress((void**)&w3t, g_w3t);
    cudaGetSymbolAddress((void**)&ew1t, g_ew1t);
    cudaGetSymbolAddress((void**)&ew2t, g_ew2t);
    cudaGetSymbolAddress((void**)&ew3t, g_ew3t);
    cudaGetSymbolAddress((void**)&attr, g_attr);

    cudaFuncSetAttribute(edge_mma_kernel,
                         cudaFuncAttributeMaxDynamicSharedMemorySize, EDGE_SMEM);
    cudaFuncSetAttribute(gemm_mma2<FDIM, H1, 1, 1>,
                         cudaFuncAttributeMaxDynamicSharedMemorySize, GEMM_SMEM);
    cudaFuncSetAttribute(gemm_mma2<H1, H2, 1, 1>,
                         cudaFuncAttributeMaxDynamicSharedMemorySize, GEMM_SMEM);
    cudaFuncSetAttribute(gemm_mma2<H2, H3, 0, 2>,
                         cudaFuncAttributeMaxDynamicSharedMemorySize, GEMM3_SMEM);

    // one-time stream/event setup (host-side resources; no device memory)
    static cudaStream_t s_edge = nullptr;
    static cudaEvent_t  ev_fork = nullptr, ev_w = nullptr, ev_join = nullptr;
    if (s_edge == nullptr) {
        cudaStreamCreateWithFlags(&s_edge, cudaStreamNonBlocking);
        cudaEventCreateWithFlags(&ev_fork, cudaEventDisableTiming);
        cudaEventCreateWithFlags(&ev_w, cudaEventDisableTiming);
        cudaEventCreateWithFlags(&ev_join, cudaEventDisableTiming);
    }

    // ---- R12 schedule: side = fused transpose -> edge prep -> edges ----
    cudaEventRecord(ev_fork, 0);
    cudaStreamWaitEvent(s_edge, ev_fork, 0);

    // main stream: roi convert (critical path for GEMM1's A operand)
    convert_f32<<<NROWS * FDIM / 4 / 256, 256>>>((const float4*)roi, (uint2*)x);

    // side stream: one fused transpose launch, then edge prep + edge kernel
    transpose3<<<dim3(16, 32, 3), dim3(32, 8), 0, s_edge>>>(
        np_w1, np_w2, np_w3, w1t, w2t, w3t);
    cudaEventRecord(ev_w, s_edge);
    prep_edge<<<64, 256, 0, s_edge>>>(ep_w1, ep_w2, ei_w, bboxes, dirs, prio,
                                      ew1t, ew2t, ew3t, attr);
    edge_mma_kernel<<<NEDGE / 256, 256, EDGE_SMEM, s_edge>>>(
        attr, eidx, ew1t, ew2t, ew3t,
        ep_b1, ep_b2, ei_b, out + NODE_OUT_ELEMS);
    cudaEventRecord(ev_join, s_edge);

    // main stream: node GEMM chain (needs transposed weights)
    cudaStreamWaitEvent(0, ev_w, 0);
    gemm_mma2<FDIM, H1, 1, 1><<<dim3(H1 / 128, NROWS / 128), 256, GEMM_SMEM>>>(
        x, w1t, np_b1, bn1_g, bn1_b, bn1_rm, bn1_rv,
        nullptr, nullptr, nullptr, h1);
    gemm_mma2<H1, H2, 1, 1><<<dim3(H2 / 128, NROWS / 128), 256, GEMM_SMEM>>>(
        h1, w2t, np_b2, bn2_g, bn2_b, bn2_rm, bn2_rv,
        nullptr, nullptr, nullptr, h2);
    gemm_mma2<H2, H3, 0, 2><<<dim3(H3 / 128, NROWS / 128), 256, GEMM3_SMEM>>>(
        h2, w3t, np_b3, nullptr, nullptr, nullptr, nullptr,
        ni_w, ni_b, out, nullptr);

    // join
    cudaStreamWaitEvent(0, ev_join, 0);
}

// round 17
// speedup vs baseline: 1.1424x; 1.0647x over previous
#include <cuda_runtime.h>
#include <cuda_bf16.h>
#include <cstdint>

// ---------------- problem constants (fixed by setup_inputs) ----------------
#define BATCH   32
#define NNODE   512
#define NROWS   (BATCH*NNODE)      // 16384
#define FDIM    1024
#define H1      512
#define H2      256
#define H3      128
#define NC      8
#define EDGES   32768              // per batch
#define NEDGE   (BATCH*EDGES)      // 1048576
#define EH      64
#define EC      10
#define CATTR   9
#define NODE_OUT_ELEMS (NROWS*NC)  // 131072

// ---------------- scratch (device globals; no allocation allowed) ----------
__device__ __nv_bfloat16 g_x[NROWS * FDIM];     // bf16 roi
__device__ __nv_bfloat16 g_h1[NROWS * H1];
__device__ __nv_bfloat16 g_h2[NROWS * H2];
__device__ __nv_bfloat16 g_w1t[H1 * FDIM];
__device__ __nv_bfloat16 g_w2t[H2 * H1];
__device__ __nv_bfloat16 g_w3t[H3 * H2];
__device__ __nv_bfloat16 g_ew1t[64 * 32];
__device__ __nv_bfloat16 g_ew2t[64 * 64];
__device__ __nv_bfloat16 g_ew3t[16 * 64];
__device__ __nv_bfloat16 g_attr[BATCH * NNODE * 10];   // precomputed node attrs

// ---------------- helpers ----------------------------------------------------
__device__ __forceinline__ uint32_t smem_u32(const void* p) {
    uint32_t a;
    asm("{ .reg .u64 t; cvta.to.shared.u64 t, %1; cvt.u32.u64 %0, t; }"
        : "=r"(a) : "l"(p));
    return a;
}
__device__ __forceinline__ void ldsm4(uint32_t addr, uint32_t* r) {
    asm volatile("ldmatrix.sync.aligned.m8n8.x4.shared.b16 {%0,%1,%2,%3}, [%4];"
                 : "=r"(r[0]), "=r"(r[1]), "=r"(r[2]), "=r"(r[3]) : "r"(addr));
}
__device__ __forceinline__ void mma16816(float* c, const uint32_t* a, const uint32_t* b) {
    asm volatile(
        "mma.sync.aligned.m16n8k16.row.col.f32.bf16.bf16.f32 "
        "{%0,%1,%2,%3}, {%4,%5,%6,%7}, {%8,%9}, {%0,%1,%2,%3};"
        : "+f"(c[0]), "+f"(c[1]), "+f"(c[2]), "+f"(c[3])
        : "r"(a[0]), "r"(a[1]), "r"(a[2]), "r"(a[3]), "r"(b[0]), "r"(b[1]));
}
__device__ __forceinline__ void sts128(uint32_t addr, uint4 v) {
    asm volatile("st.shared.v4.b32 [%0], {%1,%2,%3,%4};"
                 :: "r"(addr), "r"(v.x), "r"(v.y), "r"(v.z), "r"(v.w) : "memory");
}
__device__ __forceinline__ uint32_t pack_bf2(float a, float b) {
    __nv_bfloat162 h = __floats2bfloat162_rn(a, b);
    uint32_t u; memcpy(&u, &h, 4); return u;
}
__device__ __forceinline__ void cp16(uint32_t dst, const void* src) {
    asm volatile("cp.async.cg.shared.global [%0], [%1], 16;"
                 :: "r"(dst), "l"(src) : "memory");
}
__device__ __forceinline__ void cp_commit() {
    asm volatile("cp.async.commit_group;" ::: "memory");
}
#define CP_WAIT(n) asm volatile("cp.async.wait_group %0;" :: "n"(n) : "memory")

// ---------------- single-pass bf16 mma GEMM, cp.async 3-stage pipeline ------
// K-chunk = 64 (128-byte smem rows, c^(r&7) swizzle), 3 stages.  (R12 exact)
static constexpr int STAGE_BYTES = 32768;
static constexpr int GEMM_SMEM = 3 * STAGE_BYTES;
static constexpr int GEMM3_SMEM = GEMM_SMEM;

template<int K, int N, int EPI, int OMODE>
__global__ __launch_bounds__(256)
void gemm_mma2(const __nv_bfloat16* __restrict__ A,
               const __nv_bfloat16* __restrict__ B,
               const float* __restrict__ bias,
               const float* __restrict__ bng, const float* __restrict__ bnb,
               const float* __restrict__ bnrm, const float* __restrict__ bnrv,
               const float* __restrict__ hw,  const float* __restrict__ hb,
               float* __restrict__ Cf,
               __nv_bfloat16* __restrict__ Cb)
{
    extern __shared__ char sm_raw[];
    const uint32_t sb = smem_u32(sm_raw);
    const int tid = threadIdx.x;
    const int lane = tid & 31, w = tid >> 5;
    const int bn = blockIdx.x, bm = blockIdx.y;
    const int wr = (w & 3) * 32;
    const int wc = (w >> 2) * 64;

    const __nv_bfloat16* srcs[8];
    uint32_t dsts[8];
    #pragma unroll
    for (int i = 0; i < 8; i++) {
        int idx = i * 256 + tid;
        int slab = idx >> 10;
        int within = idx & 1023;
        int r = within >> 3, c = within & 7;
        const __nv_bfloat16* base = (slab == 0) ? A : B;
        int row0 = (slab == 0) ? bm * 128 : bn * 128;
        srcs[i] = base + (size_t)(row0 + r) * K + c * 8;
        dsts[i] = slab * 16384 + r * 128 + ((c ^ (r & 7)) << 4);
    }
    auto ISSUE = [&](int ck) {
        const uint32_t st = sb + (ck % 3) * STAGE_BYTES;
        #pragma unroll
        for (int i = 0; i < 8; i++)
            cp16(st + dsts[i], srcs[i] + ck * 64);
    };

    float acc[2][8][4];
    #pragma unroll
    for (int a = 0; a < 2; a++)
        #pragma unroll
        for (int b = 0; b < 8; b++)
            #pragma unroll
            for (int c = 0; c < 4; c++) acc[a][b][c] = 0.f;

    const int m = lane >> 3, rr = lane & 7;

    auto COMPUTE = [&](int stage) {
        const uint32_t aB = sb + stage * STAGE_BYTES;
        const uint32_t bB = aB + 16384;
        #pragma unroll
        for (int ks = 0; ks < 4; ks++) {
            const int ckb = ks * 2;
            uint32_t ah[2][4], bh[4][4];
            #pragma unroll
            for (int t2 = 0; t2 < 2; t2++) {
                const int r_l = wr + t2 * 16 + ((m & 1) << 3) + rr;
                const int c_l = ckb + (m >> 1);
                const uint32_t off = r_l * 128 + ((c_l ^ (r_l & 7)) << 4);
                ldsm4(aB + off, ah[t2]);
            }
            #pragma unroll
            for (int p = 0; p < 4; p++) {
                const int n_l = wc + p * 16 + ((m >> 1) << 3) + rr;
                const int c_l = ckb + (m & 1);
                const uint32_t off = n_l * 128 + ((c_l ^ (n_l & 7)) << 4);
                ldsm4(bB + off, bh[p]);
            }
            #pragma unroll
            for (int t2 = 0; t2 < 2; t2++)
                #pragma unroll
                for (int nt = 0; nt < 8; nt++)
                    mma16816(acc[t2][nt], ah[t2], &bh[nt >> 1][(nt & 1) * 2]);
        }
    };

    constexpr int NCH = K / 64;
    ISSUE(0); cp_commit();
    ISSUE(1); cp_commit();
    for (int c = 0; c < NCH; c++) {
        CP_WAIT(1);
        __syncthreads();
        if (c + 2 < NCH) ISSUE(c + 2);
        cp_commit();
        COMPUTE(c % 3);
    }

    float* sh3 = (float*)sm_raw;
    if (OMODE == 2) __syncthreads();

    #pragma unroll
    for (int t2 = 0; t2 < 2; t2++) {
        const int rloc = wr + t2 * 16 + (lane >> 2);
        const int row0 = bm * 128 + rloc;
        #pragma unroll
        for (int nt = 0; nt < 8; nt++) {
            const int cloc = wc + nt * 8 + 2 * (lane & 3);
            const int col = bn * 128 + cloc;
            float b0 = __ldg(&bias[col]), b1 = __ldg(&bias[col + 1]);
            float s0 = 1.f, s1 = 1.f, f0 = 0.f, f1 = 0.f;
            if (EPI) {
                s0 = __ldg(&bng[col]) * rsqrtf(__ldg(&bnrv[col]) + 1e-5f);
                f0 = __ldg(&bnb[col]) - __ldg(&bnrm[col]) * s0;
                s1 = __ldg(&bng[col + 1]) * rsqrtf(__ldg(&bnrv[col + 1]) + 1e-5f);
                f1 = __ldg(&bnb[col + 1]) - __ldg(&bnrm[col + 1]) * s1;
            }
            float v00 = acc[t2][nt][0] + b0, v01 = acc[t2][nt][1] + b1;
            float v10 = acc[t2][nt][2] + b0, v11 = acc[t2][nt][3] + b1;
            if (EPI) {
                v00 = v00 * s0 + f0; v01 = v01 * s1 + f1;
                v10 = v10 * s0 + f0; v11 = v11 * s1 + f1;
            }
            v00 = fmaxf(v00, 0.f); v01 = fmaxf(v01, 0.f);
            v10 = fmaxf(v10, 0.f); v11 = fmaxf(v11, 0.f);
            if (OMODE == 1) {
                __nv_bfloat162 h0 = __floats2bfloat162_rn(v00, v01);
                __nv_bfloat162 h1 = __floats2bfloat162_rn(v10, v11);
                *(__nv_bfloat162*)(Cb + (size_t)row0 * N + col) = h0;
                *(__nv_bfloat162*)(Cb + (size_t)(row0 + 8) * N + col) = h1;
            } else if (OMODE == 2) {
                sh3[rloc * 132 + cloc]       = v00;
                sh3[rloc * 132 + cloc + 1]   = v01;
                sh3[(rloc + 8) * 132 + cloc]     = v10;
                sh3[(rloc + 8) * 132 + cloc + 1] = v11;
            } else {
                *(float2*)(Cf + (size_t)row0 * N + col) = make_float2(v00, v01);
                *(float2*)(Cf + (size_t)(row0 + 8) * N + col) = make_float2(v10, v11);
            }
        }
    }

    if (OMODE == 2) {
        __syncthreads();
        const int base = tid * 4;
        #pragma unroll
        for (int i = 0; i < 4; i++) {
            const int idx = base + i;
            const int row = idx >> 3;
            const int j = idx & 7;
            const float* xr = &sh3[row * 132];
            float a = __ldg(&hb[j]);
            #pragma unroll 8
            for (int k = 0; k < H3; k++)
                a += xr[k] * __ldg(&hw[k * NC + j]);
            Cf[(size_t)(bm * 128 + row) * NC + j] = 1.f / (1.f + __expf(-a));
        }
    }
}

// ---------------- fp32 -> bf16 convert (for roi) ----------------------------
__global__ __launch_bounds__(256)
void convert_f32(const float4* __restrict__ in, uint2* __restrict__ ob)
{
    int i = blockIdx.x * 256 + threadIdx.x;
    float4 v = in[i];
    __nv_bfloat162 h0 = __floats2bfloat162_rn(v.x, v.y);
    __nv_bfloat162 h1 = __floats2bfloat162_rn(v.z, v.w);
    uint2 u;
    memcpy(&u.x, &h0, 4); memcpy(&u.y, &h1, 4);
    ob[i] = u;
}

// ------- fused 3-matrix transpose to bf16 (one launch, coalesced) -----------
__global__ void transpose3(const float* __restrict__ w1,
                           const float* __restrict__ w2,
                           const float* __restrict__ w3,
                           __nv_bfloat16* __restrict__ o1,
                           __nv_bfloat16* __restrict__ o2,
                           __nv_bfloat16* __restrict__ o3)
{
    __shared__ float t[32][33];
    const int z = blockIdx.z;
    const float* in; __nv_bfloat16* ob; int R, C, gx, gy;
    if (z == 0)      { in = w1; ob = o1; R = FDIM; C = H1; gx = H1/32; gy = FDIM/32; }
    else if (z == 1) { in = w2; ob = o2; R = H1;   C = H2; gx = H2/32; gy = H1/32; }
    else             { in = w3; ob = o3; R = H2;   C = H3; gx = H3/32; gy = H2/32; }
    if ((int)blockIdx.x >= gx || (int)blockIdx.y >= gy) return;

    int x = blockIdx.x * 32 + threadIdx.x;
    int y = blockIdx.y * 32 + threadIdx.y;
    #pragma unroll
    for (int i = 0; i < 32; i += 8)
        t[threadIdx.y + i][threadIdx.x] = in[(size_t)(y + i) * C + x];
    __syncthreads();
    x = blockIdx.y * 32 + threadIdx.x;
    y = blockIdx.x * 32 + threadIdx.y;
    #pragma unroll
    for (int i = 0; i < 32; i += 8)
        ob[(size_t)(y + i) * R + x] = __float2bfloat16(t[threadIdx.x][threadIdx.y + i]);
}

// ------- edge prep: weights (transpose+pad bf16) + node attr table ----------
__global__ __launch_bounds__(256)
void prep_edge(const float* __restrict__ w1, const float* __restrict__ w2,
               const float* __restrict__ wi,
               const float* __restrict__ bboxes, const float* __restrict__ dirs,
               const float* __restrict__ prio,
               __nv_bfloat16* __restrict__ o1, __nv_bfloat16* __restrict__ o2,
               __nv_bfloat16* __restrict__ o3, __nv_bfloat16* __restrict__ attr)
{
    const int t = blockIdx.x * 256 + threadIdx.x;
    const int S = gridDim.x * 256;
    for (int i = t; i < 64 * 32; i += S) {
        int n = i >> 5, k = i & 31;
        o1[i] = (k < 18) ? __float2bfloat16(w1[k * 64 + n]) : __nv_bfloat16(0.f);
    }
    for (int i = t; i < 64 * 64; i += S) {
        int n = i >> 6, k = i & 63;
        o2[i] = __float2bfloat16(w2[k * 64 + n]);
    }
    for (int i = t; i < 16 * 64; i += S) {
        int n = i >> 6, k = i & 63;
        o3[i] = (n < EC) ? __float2bfloat16(wi[k * EC + n]) : __nv_bfloat16(0.f);
    }
    const float inv = 1.f / 1024.f;
    for (int gn = t; gn < BATCH * NNODE; gn += S) {
        float4 bb = *(const float4*)&bboxes[(size_t)gn * 4];
        float4 dd = *(const float4*)&dirs[(size_t)gn * 4];
        float pr = prio[gn];
        __nv_bfloat16* a = attr + (size_t)gn * 10;
        a[0] = __float2bfloat16(bb.x * inv);
        a[1] = __float2bfloat16(bb.y * inv);
        a[2] = __float2bfloat16(bb.z * inv);
        a[3] = __float2bfloat16(bb.w * inv);
        a[4] = __float2bfloat16(dd.x);
        a[5] = __float2bfloat16(dd.y);
        a[6] = __float2bfloat16(dd.z);
        a[7] = __float2bfloat16(dd.w);
        a[8] = __float2bfloat16(pr);
        a[9] = __nv_bfloat16(0.f);
    }
}

// ---------------- edge MLP: register-chained B2B mma (R12 math core) --------
// 4 CTAs/SM target (forces <=64 regs), cp.async staging.
static constexpr int ESA_ATTR = 0;            // 512*10*2  = 10240
static constexpr int ESA_W1   = 10240;
static constexpr int ESA_W2   = 14336;
static constexpr int ESA_W3   = 22528;
static constexpr int ESA_A1   = 24576;        // 256*64 = 16384
static constexpr int EDGE_SMEM = 40960;

__global__ __launch_bounds__(256, 4)
void edge_mma_kernel(const __nv_bfloat16* __restrict__ attr,
                     const int*   __restrict__ eidx,
                     const __nv_bfloat16* __restrict__ w1t,
                     const __nv_bfloat16* __restrict__ w2t,
                     const __nv_bfloat16* __restrict__ w3t,
                     const float* __restrict__ b1,
                     const float* __restrict__ b2,
                     const float* __restrict__ bi,
                     float* __restrict__ out)
{
    extern __shared__ char sm[];
    const uint32_t sb = smem_u32(sm);
    const int tid = threadIdx.x;
    const int lane = tid & 31, w = tid >> 5;
    const int bt = blockIdx.x >> 7;
    const int e0 = (blockIdx.x & 127) * 256;

    // stage attr table + weights via cp.async (byte-identical destinations)
    {
        const uint4* asrc = (const uint4*)(attr + (size_t)bt * NNODE * 10);
        for (int i = tid; i < NNODE * 10 * 2 / 16; i += 256)
            cp16(sb + ESA_ATTR + i * 16, asrc + i);
    }
    for (int i = tid; i < 64 * 4; i += 256) {
        int r = i >> 2, c = i & 3;
        cp16(sb + ESA_W1 + r * 64 + ((c ^ ((r >> 1) & 3)) << 4),
             (const uint4*)w1t + i);
    }
    for (int i = tid; i < 64 * 8; i += 256) {
        int r = i >> 3, c = i & 7;
        cp16(sb + ESA_W2 + r * 128 + ((c ^ (r & 7)) << 4),
             (const uint4*)w2t + i);
    }
    for (int i = tid; i < 16 * 8; i += 256) {
        int r = i >> 3, c = i & 7;
        cp16(sb + ESA_W3 + r * 128 + ((c ^ (r & 7)) << 4),
             (const uint4*)w3t + i);
    }
    cp_commit();
    CP_WAIT(0);
    __syncthreads();

    __nv_bfloat16* sAttr = (__nv_bfloat16*)(sm + ESA_ATTR);
    {
        const int ebase = bt * 2 * EDGES + e0 + tid;
        const int src = eidx[ebase];
        const int dst = eidx[ebase + EDGES];
        const __nv_bfloat16* as = sAttr + src * 10;
        const __nv_bfloat16* ad = sAttr + dst * 10;
        uint16_t v[32];
        #pragma unroll
        for (int c = 0; c < 9; c++) { memcpy(&v[c], &as[c], 2); memcpy(&v[9 + c], &ad[c], 2); }
        #pragma unroll
        for (int c = 18; c < 32; c++) v[c] = 0;
        const int swz = (tid >> 1) & 3;
        #pragma unroll
        for (int ch = 0; ch < 4; ch++) {
            uint4 p;
            p.x = (uint32_t)v[ch*8+0] | ((uint32_t)v[ch*8+1] << 16);
            p.y = (uint32_t)v[ch*8+2] | ((uint32_t)v[ch*8+3] << 16);
            p.z = (uint32_t)v[ch*8+4] | ((uint32_t)v[ch*8+5] << 16);
            p.w = (uint32_t)v[ch*8+6] | ((uint32_t)v[ch*8+7] << 16);
            sts128(sb + ESA_A1 + tid * 64 + ((ch ^ swz) << 4), p);
        }
    }
    __syncwarp();

    const int m = lane >> 3, rr = lane & 7;
    const int wrow = (w >> 2) * 128 + (w & 3) * 32;
    const int t4 = 2 * (lane & 3);

    #pragma unroll
    for (int t2 = 0; t2 < 2; t2++) {
        const int rbase = wrow + t2 * 16;

        float acc1[8][4];
        #pragma unroll
        for (int b = 0; b < 8; b++)
            #pragma unroll
            for (int c = 0; c < 4; c++) acc1[b][c] = 0.f;
        #pragma unroll
        for (int k16 = 0; k16 < 2; k16++) {
            uint32_t a[4], b[4][4];
            {
                int r = rbase + ((m & 1) << 3) + rr;
                int c = k16 * 2 + (m >> 1);
                ldsm4(sb + ESA_A1 + r * 64 + ((c ^ ((r >> 1) & 3)) << 4), a);
            }
            #pragma unroll
            for (int p = 0; p < 4; p++) {
                int n = p * 16 + ((m >> 1) << 3) + rr;
                int c = k16 * 2 + (m & 1);
                ldsm4(sb + ESA_W1 + n * 64 + ((c ^ ((n >> 1) & 3)) << 4), b[p]);
            }
            #pragma unroll
            for (int nt = 0; nt < 8; nt++)
                mma16816(acc1[nt], a, &b[nt >> 1][(nt & 1) * 2]);
        }

        uint32_t a2[4][4];
        #pragma unroll
        for (int kk = 0; kk < 4; kk++) {
            const int ntA = 2 * kk, ntB = ntA + 1;
            const int colA = ntA * 8 + t4, colB = ntB * 8 + t4;
            float bA0 = __ldg(&b1[colA]), bA1 = __ldg(&b1[colA + 1]);
            float bB0 = __ldg(&b1[colB]), bB1 = __ldg(&b1[colB + 1]);
            a2[kk][0] = pack_bf2(fmaxf(acc1[ntA][0] + bA0, 0.f),
                                 fmaxf(acc1[ntA][1] + bA1, 0.f));
            a2[kk][1] = pack_bf2(fmaxf(acc1[ntA][2] + bA0, 0.f),
                                 fmaxf(acc1[ntA][3] + bA1, 0.f));
            a2[kk][2] = pack_bf2(fmaxf(acc1[ntB][0] + bB0, 0.f),
                                 fmaxf(acc1[ntB][1] + bB1, 0.f));
            a2[kk][3] = pack_bf2(fmaxf(acc1[ntB][2] + bB0, 0.f),
                                 fmaxf(acc1[ntB][3] + bB1, 0.f));
        }

        float acc2[8][4];
        #pragma unroll
        for (int b = 0; b < 8; b++)
            #pragma unroll
            for (int c = 0; c < 4; c++) acc2[b][c] = 0.f;
        #pragma unroll
        for (int kk = 0; kk < 4; kk++) {
            uint32_t b[4][4];
            #pragma unroll
            for (int p = 0; p < 4; p++) {
                int n = p * 16 + ((m >> 1) << 3) + rr;
                int c = kk * 2 + (m & 1);
                ldsm4(sb + ESA_W2 + n * 128 + ((c ^ (n & 7)) << 4), b[p]);
            }
            #pragma unroll
            for (int nt = 0; nt < 8; nt++)
                mma16816(acc2[nt], a2[kk], &b[nt >> 1][(nt & 1) * 2]);
        }

        uint32_t a3[4][4];
        #pragma unroll
        for (int kk = 0; kk < 4; kk++) {
            const int ntA = 2 * kk, ntB = ntA + 1;
            const int colA = ntA * 8 + t4, colB = ntB * 8 + t4;
            float bA0 = __ldg(&b2[colA]), bA1 = __ldg(&b2[colA + 1]);
            float bB0 = __ldg(&b2[colB]), bB1 = __ldg(&b2[colB + 1]);
            a3[kk][0] = pack_bf2(fmaxf(acc2[ntA][0] + bA0, 0.f),
                                 fmaxf(acc2[ntA][1] + bA1, 0.f));
            a3[kk][1] = pack_bf2(fmaxf(acc2[ntA][2] + bA0, 0.f),
                                 fmaxf(acc2[ntA][3] + bA1, 0.f));
            a3[kk][2] = pack_bf2(fmaxf(acc2[ntB][0] + bB0, 0.f),
                                 fmaxf(acc2[ntB][1] + bB1, 0.f));
            a3[kk][3] = pack_bf2(fmaxf(acc2[ntB][2] + bB0, 0.f),
                                 fmaxf(acc2[ntB][3] + bB1, 0.f));
        }

        float acc3[2][4];
        #pragma unroll
        for (int b = 0; b < 2; b++)
            #pragma unroll
            for (int c = 0; c < 4; c++) acc3[b][c] = 0.f;
        #pragma unroll
        for (int kk = 0; kk < 4; kk++) {
            uint32_t b[4];
            int n = ((m >> 1) << 3) + rr;
            int c = kk * 2 + (m & 1);
            ldsm4(sb + ESA_W3 + n * 128 + ((c ^ (n & 7)) << 4), b);
            mma16816(acc3[0], a3[kk], &b[0]);
            mma16816(acc3[1], a3[kk], &b[2]);
        }

        const int r0 = rbase + (lane >> 2);
        const long eg = (long)bt * EDGES + e0 + r0;
        #pragma unroll
        for (int nt = 0; nt < 2; nt++) {
            const int col = nt * 8 + t4;
            if (col < EC) {
                float bb0 = __ldg(&bi[col]), bb1 = __ldg(&bi[col + 1]);
                float s00 = 1.f / (1.f + __expf(-(acc3[nt][0] + bb0)));
                float s01 = 1.f / (1.f + __expf(-(acc3[nt][1] + bb1)));
                float s10 = 1.f / (1.f + __expf(-(acc3[nt][2] + bb0)));
                float s11 = 1.f / (1.f + __expf(-(acc3[nt][3] + bb1)));
                *(float2*)(out + eg * EC + col) = make_float2(s00, s01);
                *(float2*)(out + (eg + 8) * EC + col) = make_float2(s10, s11);
            }
        }
    }
}

// ---------------- launch ----------------------------------------------------
extern "C" void kernel_launch(void* const* d_in, const int* in_sizes, int n_in,
                              void* d_out, int out_size)
{
    const float* roi    = (const float*)d_in[0];
    const float* bboxes = (const float*)d_in[1];
    const float* dirs   = (const float*)d_in[2];
    const float* prio   = (const float*)d_in[3];
    const int*   eidx   = (const int*)  d_in[4];
    const float* np_w1  = (const float*)d_in[5];
    const float* np_b1  = (const float*)d_in[6];
    const float* bn1_g  = (const float*)d_in[7];
    const float* bn1_b  = (const float*)d_in[8];
    const float* bn1_rm = (const float*)d_in[9];
    const float* bn1_rv = (const float*)d_in[10];
    const float* np_w2  = (const float*)d_in[11];
    const float* np_b2  = (const float*)d_in[12];
    const float* bn2_g  = (const float*)d_in[13];
    const float* bn2_b  = (const float*)d_in[14];
    const float* bn2_rm = (const float*)d_in[15];
    const float* bn2_rv = (const float*)d_in[16];
    const float* np_w3  = (const float*)d_in[17];
    const float* np_b3  = (const float*)d_in[18];
    const float* ni_w   = (const float*)d_in[19];
    const float* ni_b   = (const float*)d_in[20];
    const float* ep_w1  = (const float*)d_in[21];
    const float* ep_b1  = (const float*)d_in[22];
    const float* ep_w2  = (const float*)d_in[23];
    const float* ep_b2  = (const float*)d_in[24];
    const float* ei_w   = (const float*)d_in[25];
    const float* ei_b   = (const float*)d_in[26];

    float* out = (float*)d_out;

    __nv_bfloat16 *x, *h1, *h2, *w1t, *w2t, *w3t, *ew1t, *ew2t, *ew3t, *attr;
    cudaGetSymbolAddress((void**)&x, g_x);
    cudaGetSymbolAddress((void**)&h1, g_h1);
    cudaGetSymbolAddress((void**)&h2, g_h2);
    cudaGetSymbolAddress((void**)&w1t, g_w1t);
    cudaGetSymbolAddress((void**)&w2t, g_w2t);
    cudaGetSymbolAddress((void**)&w3t, g_w3t);
    cudaGetSymbolAddress((void**)&ew1t, g_ew1t);
    cudaGetSymbolAddress((void**)&ew2t, g_ew2t);
    cudaGetSymbolAddress((void**)&ew3t, g_ew3t);
    cudaGetSymbolAddress((void**)&attr, g_attr);

    cudaFuncSetAttribute(edge_mma_kernel,
                         cudaFuncAttributeMaxDynamicSharedMemorySize, EDGE_SMEM);
    cudaFuncSetAttribute(gemm_mma2<FDIM, H1, 1, 1>,
                         cudaFuncAttributeMaxDynamicSharedMemorySize, GEMM_SMEM);
    cudaFuncSetAttribute(gemm_mma2<H1, H2, 1, 1>,
                         cudaFuncAttributeMaxDynamicSharedMemorySize, GEMM_SMEM);
    cudaFuncSetAttribute(gemm_mma2<H2, H3, 0, 2>,
                         cudaFuncAttributeMaxDynamicSharedMemorySize, GEMM3_SMEM);

    // one-time stream/event setup (host-side resources; no device memory)
    static cudaStream_t s_edge = nullptr;
    static cudaEvent_t  ev_fork = nullptr, ev_w = nullptr, ev_join = nullptr;
    if (s_edge == nullptr) {
        cudaStreamCreateWithFlags(&s_edge, cudaStreamNonBlocking);
        cudaEventCreateWithFlags(&ev_fork, cudaEventDisableTiming);
        cudaEventCreateWithFlags(&ev_w, cudaEventDisableTiming);
        cudaEventCreateWithFlags(&ev_join, cudaEventDisableTiming);
    }

    // ---- R12 schedule: side = fused transpose -> edge prep -> edges ----
    cudaEventRecord(ev_fork, 0);
    cudaStreamWaitEvent(s_edge, ev_fork, 0);

    // main stream: roi convert (critical path for GEMM1's A operand)
    convert_f32<<<NROWS * FDIM / 4 / 256, 256>>>((const float4*)roi, (uint2*)x);

    // side stream: one fused transpose launch, then edge prep + edge kernel
    transpose3<<<dim3(16, 32, 3), dim3(32, 8), 0, s_edge>>>(
        np_w1, np_w2, np_w3, w1t, w2t, w3t);
    cudaEventRecord(ev_w, s_edge);
    prep_edge<<<64, 256, 0, s_edge>>>(ep_w1, ep_w2, ei_w, bboxes, dirs, prio,
                                      ew1t, ew2t, ew3t, attr);
    edge_mma_kernel<<<NEDGE / 256, 256, EDGE_SMEM, s_edge>>>(
        attr, eidx, ew1t, ew2t, ew3t,
        ep_b1, ep_b2, ei_b, out + NODE_OUT_ELEMS);
    cudaEventRecord(ev_join, s_edge);

    // main stream: node GEMM chain (needs transposed weights)
    cudaStreamWaitEvent(0, ev_w, 0);
    gemm_mma2<FDIM, H1, 1, 1><<<dim3(H1 / 128, NROWS / 128), 256, GEMM_SMEM>>>(
        x, w1t, np_b1, bn1_g, bn1_b, bn1_rm, bn1_rv,
        nullptr, nullptr, nullptr, h1);
    gemm_mma2<H1, H2, 1, 1><<<dim3(H2 / 128, NROWS / 128), 256, GEMM_SMEM>>>(
        h1, w2t, np_b2, bn2_g, bn2_b, bn2_rm, bn2_rv,
        nullptr, nullptr, nullptr, h2);
    gemm_mma2<H2, H3, 0, 2><<<dim3(H3 / 128, NROWS / 128), 256, GEMM3_SMEM>>>(
        h2, w3t, np_b3, nullptr, nullptr, nullptr, nullptr,
        ni_w, ni_b, out, nullptr);

    // join
    cudaStreamWaitEvent(0, ev_join, 0);
}